// round 1
// baseline (speedup 1.0000x reference)
#include <cuda_runtime.h>
#include <math.h>

typedef long long TLL;

// ---------------- problem constants ----------------
// B=4, T=2048, C=1024, H=16, hd=64, D_FF=4096
#define BB   4
#define TT   2048
#define CC   1024
#define HH   16
#define HD   64
#define DFF  4096
#define ROWS (BB*TT)          // 8192

// ---------------- scratch (__device__ globals: allocation-free rule) ------
__device__ float g_h  [(TLL)ROWS*CC];        // 32 MB  ln1 out
__device__ float g_qkv[(TLL)ROWS*3*CC];      // 96 MB
__device__ float g_S  [(TLL)BB*HH*TT*TT];    // 1 GiB  attention scores
__device__ float g_y  [(TLL)ROWS*CC];        // 32 MB  attn out (pre-proj)
__device__ float g_x1 [(TLL)ROWS*CC];        // 32 MB  residual 1
__device__ float g_h2 [(TLL)ROWS*CC];        // 32 MB  ln2 out
__device__ float g_ff [(TLL)ROWS*DFF];       // 128 MB

// ---------------- helpers ----------------
__device__ __forceinline__ float gelu_f(float x) {
    const float c = 0.7978845608028654f;  // sqrt(2/pi)
    float t = tanhf(c * (x + 0.044715f * x * x * x));
    return 0.5f * x * (1.0f + t);
}

// ---------------- LayerNorm: one block per row, C=1024, 256 threads --------
__global__ void ln_kernel(const float* __restrict__ x,
                          const float* __restrict__ g,
                          const float* __restrict__ b,
                          float* __restrict__ out) {
    const int row = blockIdx.x;
    const float* xr = x + (TLL)row * CC;
    float* orow = out + (TLL)row * CC;

    float v[4];
    float s = 0.f, ss = 0.f;
#pragma unroll
    for (int i = 0; i < 4; i++) {
        v[i] = xr[threadIdx.x + 256 * i];
        s += v[i];
        ss += v[i] * v[i];
    }
#pragma unroll
    for (int o = 16; o; o >>= 1) {
        s  += __shfl_xor_sync(0xffffffffu, s, o);
        ss += __shfl_xor_sync(0xffffffffu, ss, o);
    }
    __shared__ float sh0[8], sh1[8];
    int w = threadIdx.x >> 5, l = threadIdx.x & 31;
    if (!l) { sh0[w] = s; sh1[w] = ss; }
    __syncthreads();
    if (threadIdx.x == 0) {
        float S = 0.f, SS = 0.f;
#pragma unroll
        for (int i = 0; i < 8; i++) { S += sh0[i]; SS += sh1[i]; }
        float mu = S * (1.0f / CC);
        float var = SS * (1.0f / CC) - mu * mu;
        sh0[0] = mu;
        sh1[0] = rsqrtf(var + 1e-5f);
    }
    __syncthreads();
    float mu = sh0[0], rstd = sh1[0];
#pragma unroll
    for (int i = 0; i < 4; i++) {
        int c = threadIdx.x + 256 * i;
        orow[c] = (v[i] - mu) * rstd * g[c] + b[c];
    }
}

// ---------------- Softmax over rows of length 2048 -------------------------
__global__ void softmax_kernel(float* __restrict__ S) {
    float* p = S + (TLL)blockIdx.x * TT;
    float v[8];
    float m = -1e30f;
#pragma unroll
    for (int i = 0; i < 8; i++) {
        v[i] = p[threadIdx.x + 256 * i];
        m = fmaxf(m, v[i]);
    }
#pragma unroll
    for (int o = 16; o; o >>= 1) m = fmaxf(m, __shfl_xor_sync(0xffffffffu, m, o));
    __shared__ float shm[8], shs[8];
    int w = threadIdx.x >> 5, l = threadIdx.x & 31;
    if (!l) shm[w] = m;
    __syncthreads();
    if (threadIdx.x == 0) {
        float M = shm[0];
#pragma unroll
        for (int i = 1; i < 8; i++) M = fmaxf(M, shm[i]);
        shm[0] = M;
    }
    __syncthreads();
    m = shm[0];
    float s = 0.f;
#pragma unroll
    for (int i = 0; i < 8; i++) { v[i] = expf(v[i] - m); s += v[i]; }
#pragma unroll
    for (int o = 16; o; o >>= 1) s += __shfl_xor_sync(0xffffffffu, s, o);
    if (!l) shs[w] = s;
    __syncthreads();
    if (threadIdx.x == 0) {
        float SS = 0.f;
#pragma unroll
        for (int i = 0; i < 8; i++) SS += shs[i];
        shs[0] = 1.0f / SS;
    }
    __syncthreads();
    float inv = shs[0];
#pragma unroll
    for (int i = 0; i < 8; i++) p[threadIdx.x + 256 * i] = v[i] * inv;
}

// ---------------- Generic tiled SIMT fp32 GEMM -----------------------------
// C = scale * (A @ B(^T)) [+bias] [gelu] [+residual]
// Batched over blockIdx.z: z -> (bz, hz) = (z/nH, z%nH); per-matrix offsets
// bz*bs + hz*hs applied to A, B, C (and residual, same strides as C).
// flags: 1 = +bias[col], 2 = gelu, 4 = +residual
template <int BM, int BN, int BK, int TM, int TN, bool TRANSB>
__global__ void __launch_bounds__((BM / TM) * (BN / TN))
gemm_kernel(const float* __restrict__ A, const float* __restrict__ B,
            const float* __restrict__ bias, const float* __restrict__ res,
            float* __restrict__ C,
            int K, TLL lda, TLL ldb, TLL ldc,
            TLL bsA, TLL hsA, TLL bsB, TLL hsB, TLL bsC, TLL hsC,
            int nH, float scale, int flags) {
    constexpr int NTHREADS = (BM / TM) * (BN / TN);

    const int z = blockIdx.z;
    const int bz = z / nH, hz = z - bz * nH;
    A += (TLL)bz * bsA + (TLL)hz * hsA;
    B += (TLL)bz * bsB + (TLL)hz * hsB;
    C += (TLL)bz * bsC + (TLL)hz * hsC;
    const float* R = (flags & 4) ? (res + (TLL)bz * bsC + (TLL)hz * hsC) : nullptr;

    __shared__ float As[BK][BM];
    __shared__ float Bs[BK][BN];

    const int rowBase = blockIdx.y * BM;
    const int colBase = blockIdx.x * BN;
    const int tid = threadIdx.x;
    const int tx = tid % (BN / TN);
    const int ty = tid / (BN / TN);

    float acc[TM][TN];
#pragma unroll
    for (int i = 0; i < TM; i++)
#pragma unroll
        for (int j = 0; j < TN; j++) acc[i][j] = 0.f;

    for (int k0 = 0; k0 < K; k0 += BK) {
        // stage A tile (BM x BK), transposed into As[k][m]
        for (int i = tid; i < BM * BK / 4; i += NTHREADS) {
            int r = i / (BK / 4), c4 = i % (BK / 4);
            float4 v = *(const float4*)(A + (TLL)(rowBase + r) * lda + (k0 + c4 * 4));
            As[c4 * 4 + 0][r] = v.x;
            As[c4 * 4 + 1][r] = v.y;
            As[c4 * 4 + 2][r] = v.z;
            As[c4 * 4 + 3][r] = v.w;
        }
        if (!TRANSB) {
            // B is [K, N] row-major
            for (int i = tid; i < BK * BN / 4; i += NTHREADS) {
                int r = i / (BN / 4), c4 = i % (BN / 4);
                *(float4*)&Bs[r][c4 * 4] =
                    *(const float4*)(B + (TLL)(k0 + r) * ldb + (colBase + c4 * 4));
            }
        } else {
            // B is [N, K] row-major, need Bs[k][n] = B[n][k]
            for (int i = tid; i < BN * BK / 4; i += NTHREADS) {
                int n = i / (BK / 4), c4 = i % (BK / 4);
                float4 v = *(const float4*)(B + (TLL)(colBase + n) * ldb + (k0 + c4 * 4));
                Bs[c4 * 4 + 0][n] = v.x;
                Bs[c4 * 4 + 1][n] = v.y;
                Bs[c4 * 4 + 2][n] = v.z;
                Bs[c4 * 4 + 3][n] = v.w;
            }
        }
        __syncthreads();
#pragma unroll
        for (int k = 0; k < BK; k++) {
            float rm[TM], rn[TN];
#pragma unroll
            for (int i = 0; i < TM; i += 4)
                *(float4*)&rm[i] = *(const float4*)&As[k][ty * TM + i];
#pragma unroll
            for (int j = 0; j < TN; j += 4)
                *(float4*)&rn[j] = *(const float4*)&Bs[k][tx * TN + j];
#pragma unroll
            for (int i = 0; i < TM; i++)
#pragma unroll
                for (int j = 0; j < TN; j++)
                    acc[i][j] = fmaf(rm[i], rn[j], acc[i][j]);
        }
        __syncthreads();
    }

    // epilogue
#pragma unroll
    for (int i = 0; i < TM; i++) {
        int r = rowBase + ty * TM + i;
#pragma unroll
        for (int j = 0; j < TN; j++) {
            int c = colBase + tx * TN + j;
            float v = acc[i][j] * scale;
            if (flags & 1) v += bias[c];
            if (flags & 2) v = gelu_f(v);
            if (flags & 4) v += R[(TLL)r * ldc + c];
            C[(TLL)r * ldc + c] = v;
        }
    }
}

// ---------------- launch ----------------
extern "C" void kernel_launch(void* const* d_in, const int* in_sizes, int n_in,
                              void* d_out, int out_size) {
    const float* x          = (const float*)d_in[0];
    const float* ln1_g      = (const float*)d_in[1];
    const float* ln1_b      = (const float*)d_in[2];
    const float* w_qkv      = (const float*)d_in[3];
    const float* b_qkv      = (const float*)d_in[4];
    const float* w_attnproj = (const float*)d_in[5];
    const float* b_attnproj = (const float*)d_in[6];
    const float* ln2_g      = (const float*)d_in[7];
    const float* ln2_b      = (const float*)d_in[8];
    const float* w_fc       = (const float*)d_in[9];
    const float* b_fc       = (const float*)d_in[10];
    const float* w_proj     = (const float*)d_in[11];
    const float* b_proj     = (const float*)d_in[12];
    float* out = (float*)d_out;

    float *h, *qkv, *S, *y, *x1, *h2, *ff;
    cudaGetSymbolAddress((void**)&h,   g_h);
    cudaGetSymbolAddress((void**)&qkv, g_qkv);
    cudaGetSymbolAddress((void**)&S,   g_S);
    cudaGetSymbolAddress((void**)&y,   g_y);
    cudaGetSymbolAddress((void**)&x1,  g_x1);
    cudaGetSymbolAddress((void**)&h2,  g_h2);
    cudaGetSymbolAddress((void**)&ff,  g_ff);

    // 1) h = LN1(x)
    ln_kernel<<<ROWS, 256>>>(x, ln1_g, ln1_b, h);

    // 2) qkv = h @ w_qkv + b_qkv          [8192 x 3072] K=1024
    gemm_kernel<128, 128, 16, 8, 8, false>
        <<<dim3(3 * CC / 128, ROWS / 128, 1), 256>>>(
            h, w_qkv, b_qkv, nullptr, qkv,
            CC, CC, 3 * CC, 3 * CC,
            0, 0, 0, 0, 0, 0, 1, 1.0f, /*bias*/ 1);

    // 3) S[b,h] = Q[b,h] @ K[b,h]^T * (1/8)   batched 64x: M=N=2048, K=64 (NT)
    gemm_kernel<128, 128, 16, 8, 8, true>
        <<<dim3(TT / 128, TT / 128, BB * HH), 256>>>(
            qkv /*Q*/, qkv + CC /*K*/, nullptr, nullptr, S,
            HD, 3 * CC, 3 * CC, TT,
            (TLL)TT * 3 * CC, HD,               // A strides (batch, head)
            (TLL)TT * 3 * CC, HD,               // B strides
            (TLL)HH * TT * TT, (TLL)TT * TT,    // C strides
            HH, 0.125f, 0);

    // 4) softmax rows
    softmax_kernel<<<BB * HH * TT, 256>>>(S);

    // 5) y[b,:,h*64:(h+1)*64] = P[b,h] @ V[b,h]   batched 64x: M=2048,N=64,K=2048
    gemm_kernel<128, 64, 16, 8, 4, false>
        <<<dim3(1, TT / 128, BB * HH), 256>>>(
            S, qkv + 2 * CC /*V*/, nullptr, nullptr, y,
            TT, TT, 3 * CC, CC,
            (TLL)HH * TT * TT, (TLL)TT * TT,    // A = scores
            (TLL)TT * 3 * CC, HD,               // B = V
            (TLL)TT * CC, HD,                   // C = y (head col offset)
            HH, 1.0f, 0);

    // 6) x1 = x + y @ w_attnproj + b_attnproj     [8192 x 1024] K=1024
    gemm_kernel<128, 128, 16, 8, 8, false>
        <<<dim3(CC / 128, ROWS / 128, 1), 256>>>(
            y, w_attnproj, b_attnproj, x, x1,
            CC, CC, CC, CC,
            0, 0, 0, 0, 0, 0, 1, 1.0f, /*bias|res*/ 1 | 4);

    // 7) h2 = LN2(x1)
    ln_kernel<<<ROWS, 256>>>(x1, ln2_g, ln2_b, h2);

    // 8) ff = gelu(h2 @ w_fc + b_fc)              [8192 x 4096] K=1024
    gemm_kernel<128, 128, 16, 8, 8, false>
        <<<dim3(DFF / 128, ROWS / 128, 1), 256>>>(
            h2, w_fc, b_fc, nullptr, ff,
            CC, CC, DFF, DFF,
            0, 0, 0, 0, 0, 0, 1, 1.0f, /*bias|gelu*/ 1 | 2);

    // 9) out = x1 + ff @ w_proj + b_proj          [8192 x 1024] K=4096
    gemm_kernel<128, 128, 16, 8, 8, false>
        <<<dim3(CC / 128, ROWS / 128, 1), 256>>>(
            ff, w_proj, b_proj, x1, out,
            DFF, DFF, CC, CC,
            0, 0, 0, 0, 0, 0, 1, 1.0f, /*bias|res*/ 1 | 4);
}

// round 3
// speedup vs baseline: 1.5944x; 1.5944x over previous
#include <cuda_runtime.h>
#include <math.h>
#include <stdint.h>

typedef long long TLL;

// ---------------- problem constants ----------------
#define BB   4
#define TT   2048
#define CC   1024
#define HH   16
#define HD   64
#define DFF  4096
#define ROWS (BB*TT)          // 8192

// ---------------- scratch ----------------
__device__ float g_h    [(TLL)ROWS*CC];
__device__ float g_qkv  [(TLL)ROWS*3*CC];
__device__ float g_S    [(TLL)BB*HH*TT*TT];     // 1 GiB scores
__device__ float g_y    [(TLL)ROWS*CC];
__device__ float g_x1   [(TLL)ROWS*CC];
__device__ float g_h2   [(TLL)ROWS*CC];
__device__ float g_ff   [(TLL)ROWS*DFF];
__device__ float g_wqkvT[(TLL)3*CC*CC];
__device__ float g_wapT [(TLL)CC*CC];
__device__ float g_wfcT [(TLL)DFF*CC];
__device__ float g_wprjT[(TLL)CC*DFF];
__device__ float g_vT   [(TLL)BB*HH*HD*TT];     // per (b,h): [64 x 2048]

// ---------------- helpers ----------------
__device__ __forceinline__ uint32_t smem_u32(const void* p) {
    return (uint32_t)__cvta_generic_to_shared(p);
}
__device__ __forceinline__ float gelu_f(float x) {
    const float c = 0.7978845608028654f;
    float t = tanhf(c * (x + 0.044715f * x * x * x));
    return 0.5f * x * (1.0f + t);
}
__device__ __forceinline__ void split_tf32(float v, uint32_t& hi, uint32_t& lo) {
    uint32_t h;
    asm("cvt.rna.tf32.f32 %0, %1;" : "=r"(h) : "f"(v));
    float r = v - __uint_as_float(h);
    uint32_t l;
    asm("cvt.rna.tf32.f32 %0, %1;" : "=r"(l) : "f"(r));
    hi = h; lo = l;
}
__device__ __forceinline__ void mma_tf32(float* d, const uint32_t* a, const uint32_t* b) {
    asm volatile(
        "mma.sync.aligned.m16n8k8.row.col.f32.tf32.tf32.f32 "
        "{%0,%1,%2,%3}, {%4,%5,%6,%7}, {%8,%9}, {%0,%1,%2,%3};"
        : "+f"(d[0]), "+f"(d[1]), "+f"(d[2]), "+f"(d[3])
        : "r"(a[0]), "r"(a[1]), "r"(a[2]), "r"(a[3]), "r"(b[0]), "r"(b[1]));
}

// ---------------- LayerNorm ----------------
__global__ void ln_kernel(const float* __restrict__ x,
                          const float* __restrict__ g,
                          const float* __restrict__ b,
                          float* __restrict__ out) {
    const int row = blockIdx.x;
    const float* xr = x + (TLL)row * CC;
    float* orow = out + (TLL)row * CC;
    float v[4]; float s = 0.f, ss = 0.f;
#pragma unroll
    for (int i = 0; i < 4; i++) {
        v[i] = xr[threadIdx.x + 256 * i];
        s += v[i]; ss += v[i] * v[i];
    }
#pragma unroll
    for (int o = 16; o; o >>= 1) {
        s  += __shfl_xor_sync(0xffffffffu, s, o);
        ss += __shfl_xor_sync(0xffffffffu, ss, o);
    }
    __shared__ float sh0[8], sh1[8];
    int w = threadIdx.x >> 5, l = threadIdx.x & 31;
    if (!l) { sh0[w] = s; sh1[w] = ss; }
    __syncthreads();
    if (threadIdx.x == 0) {
        float S = 0.f, SS = 0.f;
#pragma unroll
        for (int i = 0; i < 8; i++) { S += sh0[i]; SS += sh1[i]; }
        float mu = S * (1.0f / CC);
        float var = SS * (1.0f / CC) - mu * mu;
        sh0[0] = mu; sh1[0] = rsqrtf(var + 1e-5f);
    }
    __syncthreads();
    float mu = sh0[0], rstd = sh1[0];
#pragma unroll
    for (int i = 0; i < 4; i++) {
        int c = threadIdx.x + 256 * i;
        orow[c] = (v[i] - mu) * rstd * g[c] + b[c];
    }
}

// ---------------- Softmax (rows of 2048) ----------------
__global__ void softmax_kernel(float* __restrict__ S) {
    float* p = S + (TLL)blockIdx.x * TT;
    float v[8]; float m = -1e30f;
#pragma unroll
    for (int i = 0; i < 8; i++) { v[i] = p[threadIdx.x + 256 * i]; m = fmaxf(m, v[i]); }
#pragma unroll
    for (int o = 16; o; o >>= 1) m = fmaxf(m, __shfl_xor_sync(0xffffffffu, m, o));
    __shared__ float shm[8], shs[8];
    int w = threadIdx.x >> 5, l = threadIdx.x & 31;
    if (!l) shm[w] = m;
    __syncthreads();
    if (threadIdx.x == 0) {
        float M = shm[0];
#pragma unroll
        for (int i = 1; i < 8; i++) M = fmaxf(M, shm[i]);
        shm[0] = M;
    }
    __syncthreads();
    m = shm[0];
    float s = 0.f;
#pragma unroll
    for (int i = 0; i < 8; i++) { v[i] = expf(v[i] - m); s += v[i]; }
#pragma unroll
    for (int o = 16; o; o >>= 1) s += __shfl_xor_sync(0xffffffffu, s, o);
    if (!l) shs[w] = s;
    __syncthreads();
    if (threadIdx.x == 0) {
        float SS = 0.f;
#pragma unroll
        for (int i = 0; i < 8; i++) SS += shs[i];
        shs[0] = 1.0f / SS;
    }
    __syncthreads();
    float inv = shs[0];
#pragma unroll
    for (int i = 0; i < 8; i++) p[threadIdx.x + 256 * i] = v[i] * inv;
}

// ---------------- transpose: out[n][k] = in[k][n] -------------------------
__global__ void transpose_kernel(const float* __restrict__ in, float* __restrict__ out,
                                 TLL ldin, TLL ldout,
                                 TLL bsIn, TLL hsIn, TLL zsOut, int nH) {
    __shared__ float t[32][33];
    int z = blockIdx.z, bz = z / nH, hz = z - bz * nH;
    const float* ip = in + (TLL)bz * bsIn + (TLL)hz * hsIn;
    float* op = out + (TLL)z * zsOut;
    int k0 = blockIdx.y * 32, n0 = blockIdx.x * 32;
    int tx = threadIdx.x, ty = threadIdx.y;
#pragma unroll
    for (int i = 0; i < 32; i += 8)
        t[ty + i][tx] = ip[(TLL)(k0 + ty + i) * ldin + (n0 + tx)];
    __syncthreads();
#pragma unroll
    for (int i = 0; i < 32; i += 8)
        op[(TLL)(n0 + ty + i) * ldout + (k0 + tx)] = t[tx][ty + i];
}

// ---------------- 3xTF32 mma.sync GEMM -------------------------------------
// D[m][n] = scale * sum_k A[m][k]*B[n][k] (K-major operands), tile 128 x BN,
// BK=16, 256 threads, warp grid 2x4 (warp tile 64 x BN/4).
// flags: 1=+bias[col], 2=gelu, 4=+residual
template <int BN>
__global__ void __launch_bounds__(256)
mm_gemm(const float* __restrict__ A, const float* __restrict__ Bm,
        const float* __restrict__ bias, const float* __restrict__ res,
        float* __restrict__ C, int K,
        TLL lda, TLL ldb, TLL ldc,
        TLL bsA, TLL hsA, TLL bsB, TLL hsB, TLL bsC, TLL hsC,
        int nH, float scale, int flags) {
    constexpr int BK  = 16;
    constexpr int PAD = 20;             // floats per smem row (conflict-free)
    constexpr int WTN = BN / 4;         // warp tile N
    constexpr int NI  = WTN / 8;        // n8 tiles per warp

    __shared__ float As[2][128 * PAD];
    __shared__ float Bs[2][BN * PAD];

    const int tid = threadIdx.x, wid = tid >> 5, lane = tid & 31;
    const int wm = wid & 1, wn = wid >> 1;     // 2 x 4 warp grid
    const int lq = lane >> 2, lr = lane & 3;

    const int z = blockIdx.z, bz = z / nH, hz = z - bz * nH;
    A  += (TLL)bz * bsA + (TLL)hz * hsA;
    Bm += (TLL)bz * bsB + (TLL)hz * hsB;
    C  += (TLL)bz * bsC + (TLL)hz * hsC;
    const float* R = (flags & 4) ? res + (TLL)bz * bsC + (TLL)hz * hsC : nullptr;

    const TLL rowBase = (TLL)blockIdx.y * 128;
    const TLL colBase = (TLL)blockIdx.x * BN;

    float acc[4][NI][4];
#pragma unroll
    for (int i = 0; i < 4; i++)
#pragma unroll
        for (int j = 0; j < NI; j++)
#pragma unroll
            for (int q = 0; q < 4; q++) acc[i][j][q] = 0.f;

    auto stage = [&](int buf, int k0) {
#pragma unroll
        for (int t = 0; t < 2; t++) {              // A: 128 rows x 4 x 16B
            int idx = tid + (t << 8);
            int r = idx >> 2, c4 = idx & 3;
            const float* gp = A + (rowBase + r) * lda + (k0 + c4 * 4);
            uint32_t so = smem_u32(&As[buf][r * PAD + c4 * 4]);
            asm volatile("cp.async.cg.shared.global [%0], [%1], 16;" :: "r"(so), "l"(gp));
        }
#pragma unroll
        for (int t = 0; t < BN / 64; t++) {        // B: BN rows x 4 x 16B
            int idx = tid + (t << 8);
            int r = idx >> 2, c4 = idx & 3;
            const float* gp = Bm + (colBase + r) * ldb + (k0 + c4 * 4);
            uint32_t so = smem_u32(&Bs[buf][r * PAD + c4 * 4]);
            asm volatile("cp.async.cg.shared.global [%0], [%1], 16;" :: "r"(so), "l"(gp));
        }
        asm volatile("cp.async.commit_group;");
    };

    const int iters = K / BK;
    int buf = 0;
    stage(0, 0);

    for (int it = 0; it < iters; ++it) {
        if (it + 1 < iters) {
            stage(buf ^ 1, (it + 1) * BK);
            asm volatile("cp.async.wait_group 1;" ::: "memory");
        } else {
            asm volatile("cp.async.wait_group 0;" ::: "memory");
        }
        __syncthreads();

        const float* sA = As[buf];
        const float* sB = Bs[buf];
#pragma unroll
        for (int ks = 0; ks < 2; ks++) {
            uint32_t Ahi[4][4], Alo[4][4];
#pragma unroll
            for (int mi = 0; mi < 4; mi++) {
                int base = (wm * 64 + mi * 16 + lq) * PAD + ks * 8 + lr;
                split_tf32(sA[base],            Ahi[mi][0], Alo[mi][0]);
                split_tf32(sA[base + 8 * PAD],  Ahi[mi][1], Alo[mi][1]);
                split_tf32(sA[base + 4],        Ahi[mi][2], Alo[mi][2]);
                split_tf32(sA[base + 8 * PAD + 4], Ahi[mi][3], Alo[mi][3]);
            }
            uint32_t Bhi[NI][2], Blo[NI][2];
#pragma unroll
            for (int ni = 0; ni < NI; ni++) {
                int base = (wn * WTN + ni * 8 + lq) * PAD + ks * 8 + lr;
                split_tf32(sB[base],     Bhi[ni][0], Blo[ni][0]);
                split_tf32(sB[base + 4], Bhi[ni][1], Blo[ni][1]);
            }
#pragma unroll
            for (int mi = 0; mi < 4; mi++)
#pragma unroll
                for (int ni = 0; ni < NI; ni++) {
                    mma_tf32(acc[mi][ni], Alo[mi], Bhi[ni]);
                    mma_tf32(acc[mi][ni], Ahi[mi], Blo[ni]);
                    mma_tf32(acc[mi][ni], Ahi[mi], Bhi[ni]);
                }
        }
        __syncthreads();
        buf ^= 1;
    }

    // ---------------- epilogue ----------------
#pragma unroll
    for (int mi = 0; mi < 4; mi++) {
        TLL r0 = rowBase + wm * 64 + mi * 16 + lq;
#pragma unroll
        for (int ni = 0; ni < NI; ni++) {
            TLL c = colBase + wn * WTN + ni * 8 + lr * 2;
            float2 v0 = { acc[mi][ni][0] * scale, acc[mi][ni][1] * scale };
            float2 v1 = { acc[mi][ni][2] * scale, acc[mi][ni][3] * scale };
            if (flags & 1) {
                float2 bb = *(const float2*)(bias + c);
                v0.x += bb.x; v0.y += bb.y; v1.x += bb.x; v1.y += bb.y;
            }
            if (flags & 2) {
                v0.x = gelu_f(v0.x); v0.y = gelu_f(v0.y);
                v1.x = gelu_f(v1.x); v1.y = gelu_f(v1.y);
            }
            if (flags & 4) {
                float2 ra = *(const float2*)(R + r0 * ldc + c);
                float2 rb = *(const float2*)(R + (r0 + 8) * ldc + c);
                v0.x += ra.x; v0.y += ra.y; v1.x += rb.x; v1.y += rb.y;
            }
            *(float2*)(C + r0 * ldc + c) = v0;
            *(float2*)(C + (r0 + 8) * ldc + c) = v1;
        }
    }
}

// ---------------- launch ----------------
extern "C" void kernel_launch(void* const* d_in, const int* in_sizes, int n_in,
                              void* d_out, int out_size) {
    const float* x          = (const float*)d_in[0];
    const float* ln1_g      = (const float*)d_in[1];
    const float* ln1_b      = (const float*)d_in[2];
    const float* w_qkv      = (const float*)d_in[3];
    const float* b_qkv      = (const float*)d_in[4];
    const float* w_attnproj = (const float*)d_in[5];
    const float* b_attnproj = (const float*)d_in[6];
    const float* ln2_g      = (const float*)d_in[7];
    const float* ln2_b      = (const float*)d_in[8];
    const float* w_fc       = (const float*)d_in[9];
    const float* b_fc       = (const float*)d_in[10];
    const float* w_proj     = (const float*)d_in[11];
    const float* b_proj     = (const float*)d_in[12];
    float* out = (float*)d_out;

    float *h, *qkv, *S, *y, *x1, *h2, *ff;
    float *wqkvT, *wapT, *wfcT, *wprjT, *vT;
    cudaGetSymbolAddress((void**)&h,     g_h);
    cudaGetSymbolAddress((void**)&qkv,   g_qkv);
    cudaGetSymbolAddress((void**)&S,     g_S);
    cudaGetSymbolAddress((void**)&y,     g_y);
    cudaGetSymbolAddress((void**)&x1,    g_x1);
    cudaGetSymbolAddress((void**)&h2,    g_h2);
    cudaGetSymbolAddress((void**)&ff,    g_ff);
    cudaGetSymbolAddress((void**)&wqkvT, g_wqkvT);
    cudaGetSymbolAddress((void**)&wapT,  g_wapT);
    cudaGetSymbolAddress((void**)&wfcT,  g_wfcT);
    cudaGetSymbolAddress((void**)&wprjT, g_wprjT);
    cudaGetSymbolAddress((void**)&vT,    g_vT);

    dim3 tb(32, 8);
    transpose_kernel<<<dim3(3 * CC / 32, CC / 32, 1), tb>>>(w_qkv, wqkvT, 3 * CC, CC, 0, 0, 0, 1);
    transpose_kernel<<<dim3(CC / 32, CC / 32, 1), tb>>>(w_attnproj, wapT, CC, CC, 0, 0, 0, 1);
    transpose_kernel<<<dim3(DFF / 32, CC / 32, 1), tb>>>(w_fc, wfcT, DFF, CC, 0, 0, 0, 1);
    transpose_kernel<<<dim3(CC / 32, DFF / 32, 1), tb>>>(w_proj, wprjT, CC, DFF, 0, 0, 0, 1);

    // 1) h = LN1(x)
    ln_kernel<<<ROWS, 256>>>(x, ln1_g, ln1_b, h);

    // 2) qkv = h @ w_qkv + b_qkv
    mm_gemm<128><<<dim3(3 * CC / 128, ROWS / 128, 1), 256>>>(
        h, wqkvT, b_qkv, nullptr, qkv, CC,
        CC, CC, 3 * CC, 0, 0, 0, 0, 0, 0, 1, 1.0f, 1);

    // 3) S = Q @ K^T / 8  (batched 64)
    mm_gemm<128><<<dim3(TT / 128, TT / 128, BB * HH), 256>>>(
        qkv, qkv + CC, nullptr, nullptr, S, HD,
        3 * CC, 3 * CC, TT,
        (TLL)TT * 3 * CC, HD, (TLL)TT * 3 * CC, HD,
        (TLL)HH * TT * TT, (TLL)TT * TT, HH, 0.125f, 0);

    // 4) softmax
    softmax_kernel<<<BB * HH * TT, 256>>>(S);

    // 5) vT[b,h] = V[b,h]^T
    transpose_kernel<<<dim3(HD / 32, TT / 32, BB * HH), tb>>>(
        qkv + 2 * CC, vT, 3 * CC, TT,
        (TLL)TT * 3 * CC, HD, (TLL)HD * TT, HH);

    // 6) y = P @ V  (batched 64, N=64)
    mm_gemm<64><<<dim3(1, TT / 128, BB * HH), 256>>>(
        S, vT, nullptr, nullptr, y, TT,
        TT, TT, CC,
        (TLL)HH * TT * TT, (TLL)TT * TT,
        (TLL)HH * HD * TT, (TLL)HD * TT,
        (TLL)TT * CC, HD, HH, 1.0f, 0);

    // 7) x1 = x + y @ w_attnproj + b
    mm_gemm<128><<<dim3(CC / 128, ROWS / 128, 1), 256>>>(
        y, wapT, b_attnproj, x, x1, CC,
        CC, CC, CC, 0, 0, 0, 0, 0, 0, 1, 1.0f, 1 | 4);

    // 8) h2 = LN2(x1)
    ln_kernel<<<ROWS, 256>>>(x1, ln2_g, ln2_b, h2);

    // 9) ff = gelu(h2 @ w_fc + b_fc)
    mm_gemm<128><<<dim3(DFF / 128, ROWS / 128, 1), 256>>>(
        h2, wfcT, b_fc, nullptr, ff, CC,
        CC, CC, DFF, 0, 0, 0, 0, 0, 0, 1, 1.0f, 1 | 2);

    // 10) out = x1 + ff @ w_proj + b_proj
    mm_gemm<128><<<dim3(CC / 128, ROWS / 128, 1), 256>>>(
        ff, wprjT, b_proj, x1, out, DFF,
        DFF, DFF, CC, 0, 0, 0, 0, 0, 0, 1, 1.0f, 1 | 4);
}

// round 5
// speedup vs baseline: 2.8323x; 1.7764x over previous
#include <cuda_runtime.h>
#include <cuda_bf16.h>
#include <math.h>
#include <stdint.h>

typedef long long TLL;
typedef __nv_bfloat16 bf16;

// ---------------- problem constants ----------------
#define BB   4
#define TT   2048
#define CC   1024
#define HH   16
#define HD   64
#define DFF  4096
#define ROWS (BB*TT)          // 8192

// ---------------- scratch ----------------
__device__ float g_S   [(TLL)BB*HH*TT*TT];      // 1 GiB scores (fp32)
__device__ float g_x1  [(TLL)ROWS*CC];          // residual 1 (fp32)

__device__ bf16 g_h_hi [(TLL)ROWS*CC],      g_h_lo [(TLL)ROWS*CC];
__device__ bf16 g_qkv_hi[(TLL)ROWS*3*CC],   g_qkv_lo[(TLL)ROWS*3*CC];
__device__ bf16 g_P_hi [(TLL)BB*HH*TT*TT],  g_P_lo [(TLL)BB*HH*TT*TT];   // 512 MB
__device__ bf16 g_vT_hi[(TLL)BB*HH*HD*TT],  g_vT_lo[(TLL)BB*HH*HD*TT];
__device__ bf16 g_y_hi [(TLL)ROWS*CC],      g_y_lo [(TLL)ROWS*CC];
__device__ bf16 g_h2_hi[(TLL)ROWS*CC],      g_h2_lo[(TLL)ROWS*CC];
__device__ bf16 g_ff_hi[(TLL)ROWS*DFF],     g_ff_lo[(TLL)ROWS*DFF];
__device__ bf16 g_wqkvT_hi[(TLL)3*CC*CC],   g_wqkvT_lo[(TLL)3*CC*CC];
__device__ bf16 g_wapT_hi [(TLL)CC*CC],     g_wapT_lo [(TLL)CC*CC];
__device__ bf16 g_wfcT_hi [(TLL)DFF*CC],    g_wfcT_lo [(TLL)DFF*CC];
__device__ bf16 g_wprjT_hi[(TLL)CC*DFF],    g_wprjT_lo[(TLL)CC*DFF];

// ---------------- helpers ----------------
__device__ __forceinline__ uint32_t smem_u32(const void* p) {
    return (uint32_t)__cvta_generic_to_shared(p);
}
__device__ __forceinline__ float gelu_f(float x) {
    const float c = 0.7978845608028654f;
    float t = tanhf(c * (x + 0.044715f * x * x * x));
    return 0.5f * x * (1.0f + t);
}
__device__ __forceinline__ void split_bf(float v, bf16& h, bf16& l) {
    h = __float2bfloat16(v);
    l = __float2bfloat16(v - __bfloat162float(h));
}
__device__ __forceinline__ void mma_bf16(float* d, const uint32_t* a, const uint32_t* b) {
    asm volatile(
        "mma.sync.aligned.m16n8k16.row.col.f32.bf16.bf16.f32 "
        "{%0,%1,%2,%3}, {%4,%5,%6,%7}, {%8,%9}, {%0,%1,%2,%3};"
        : "+f"(d[0]), "+f"(d[1]), "+f"(d[2]), "+f"(d[3])
        : "r"(a[0]), "r"(a[1]), "r"(a[2]), "r"(a[3]), "r"(b[0]), "r"(b[1]));
}
#define LDSM4(r, addr) \
    asm volatile("ldmatrix.sync.aligned.m8n8.x4.shared.b16 {%0,%1,%2,%3}, [%4];" \
        : "=r"((r)[0]), "=r"((r)[1]), "=r"((r)[2]), "=r"((r)[3]) : "r"(addr))
#define LDSM2(r, addr) \
    asm volatile("ldmatrix.sync.aligned.m8n8.x2.shared.b16 {%0,%1}, [%2];" \
        : "=r"((r)[0]), "=r"((r)[1]) : "r"(addr))
#define CP16(dst, src) \
    asm volatile("cp.async.cg.shared.global [%0], [%1], 16;" :: "r"(dst), "l"(src))

// ---------------- LayerNorm -> dual bf16 ----------------
__global__ void ln_dual(const float* __restrict__ x,
                        const float* __restrict__ g,
                        const float* __restrict__ b,
                        bf16* __restrict__ oh, bf16* __restrict__ ol) {
    const int row = blockIdx.x;
    const float* xr = x + (TLL)row * CC;
    float v[4]; float s = 0.f, ss = 0.f;
#pragma unroll
    for (int i = 0; i < 4; i++) {
        v[i] = xr[threadIdx.x + 256 * i];
        s += v[i]; ss += v[i] * v[i];
    }
#pragma unroll
    for (int o = 16; o; o >>= 1) {
        s  += __shfl_xor_sync(0xffffffffu, s, o);
        ss += __shfl_xor_sync(0xffffffffu, ss, o);
    }
    __shared__ float sh0[8], sh1[8];
    int w = threadIdx.x >> 5, l = threadIdx.x & 31;
    if (!l) { sh0[w] = s; sh1[w] = ss; }
    __syncthreads();
    if (threadIdx.x == 0) {
        float S = 0.f, SS = 0.f;
#pragma unroll
        for (int i = 0; i < 8; i++) { S += sh0[i]; SS += sh1[i]; }
        float mu = S * (1.0f / CC);
        float var = SS * (1.0f / CC) - mu * mu;
        sh0[0] = mu; sh1[0] = rsqrtf(var + 1e-5f);
    }
    __syncthreads();
    float mu = sh0[0], rstd = sh1[0];
#pragma unroll
    for (int i = 0; i < 4; i++) {
        int c = threadIdx.x + 256 * i;
        float o = (v[i] - mu) * rstd * g[c] + b[c];
        bf16 hi, lo; split_bf(o, hi, lo);
        oh[(TLL)row * CC + c] = hi;
        ol[(TLL)row * CC + c] = lo;
    }
}

// ---------------- Softmax (rows of 2048) -> dual bf16 ----------------
__global__ void softmax_dual(const float* __restrict__ S,
                             bf16* __restrict__ Ph, bf16* __restrict__ Pl) {
    const float* p = S + (TLL)blockIdx.x * TT;
    bf16* oh = Ph + (TLL)blockIdx.x * TT;
    bf16* ol = Pl + (TLL)blockIdx.x * TT;
    float v[8]; float m = -1e30f;
#pragma unroll
    for (int i = 0; i < 8; i++) { v[i] = p[threadIdx.x + 256 * i]; m = fmaxf(m, v[i]); }
#pragma unroll
    for (int o = 16; o; o >>= 1) m = fmaxf(m, __shfl_xor_sync(0xffffffffu, m, o));
    __shared__ float shm[8], shs[8];
    int w = threadIdx.x >> 5, l = threadIdx.x & 31;
    if (!l) shm[w] = m;
    __syncthreads();
    if (threadIdx.x == 0) {
        float M = shm[0];
#pragma unroll
        for (int i = 1; i < 8; i++) M = fmaxf(M, shm[i]);
        shm[0] = M;
    }
    __syncthreads();
    m = shm[0];
    float s = 0.f;
#pragma unroll
    for (int i = 0; i < 8; i++) { v[i] = expf(v[i] - m); s += v[i]; }
#pragma unroll
    for (int o = 16; o; o >>= 1) s += __shfl_xor_sync(0xffffffffu, s, o);
    if (!l) shs[w] = s;
    __syncthreads();
    if (threadIdx.x == 0) {
        float SS = 0.f;
#pragma unroll
        for (int i = 0; i < 8; i++) SS += shs[i];
        shs[0] = 1.0f / SS;
    }
    __syncthreads();
    float inv = shs[0];
#pragma unroll
    for (int i = 0; i < 8; i++) {
        bf16 hi, lo; split_bf(v[i] * inv, hi, lo);
        oh[threadIdx.x + 256 * i] = hi;
        ol[threadIdx.x + 256 * i] = lo;
    }
}

// ---------------- transpose fp32 -> dual bf16 ([K,N] -> [N,K]) -------------
__global__ void transpose_conv(const float* __restrict__ in,
                               bf16* __restrict__ oh, bf16* __restrict__ ol,
                               int ldin, int ldout) {
    __shared__ float t[32][33];
    int k0 = blockIdx.y * 32, n0 = blockIdx.x * 32;
    int tx = threadIdx.x, ty = threadIdx.y;
#pragma unroll
    for (int i = 0; i < 32; i += 8)
        t[ty + i][tx] = in[(TLL)(k0 + ty + i) * ldin + (n0 + tx)];
    __syncthreads();
#pragma unroll
    for (int i = 0; i < 32; i += 8) {
        bf16 hi, lo; split_bf(t[tx][ty + i], hi, lo);
        TLL o = (TLL)(n0 + ty + i) * ldout + (k0 + tx);
        oh[o] = hi; ol[o] = lo;
    }
}

// ---------------- transpose dual bf16 -> dual bf16 (for V^T) ---------------
__global__ void transpose_dual(const bf16* __restrict__ ih, const bf16* __restrict__ il,
                               bf16* __restrict__ oh, bf16* __restrict__ ol,
                               TLL ldin, TLL ldout,
                               TLL bsIn, TLL hsIn, TLL zsOut, int nH) {
    __shared__ bf16 th[32][33], tl[32][33];
    int z = blockIdx.z, bz = z / nH, hz = z - bz * nH;
    TLL ibase = (TLL)bz * bsIn + (TLL)hz * hsIn;
    TLL obase = (TLL)z * zsOut;
    int k0 = blockIdx.y * 32, n0 = blockIdx.x * 32;
    int tx = threadIdx.x, ty = threadIdx.y;
#pragma unroll
    for (int i = 0; i < 32; i += 8) {
        TLL s = ibase + (TLL)(k0 + ty + i) * ldin + (n0 + tx);
        th[ty + i][tx] = ih[s];
        tl[ty + i][tx] = il[s];
    }
    __syncthreads();
#pragma unroll
    for (int i = 0; i < 32; i += 8) {
        TLL d = obase + (TLL)(n0 + ty + i) * ldout + (k0 + tx);
        oh[d] = th[tx][ty + i];
        ol[d] = tl[tx][ty + i];
    }
}

// ---------------- bf16x3 mma.sync GEMM -------------------------------------
// D[m][n] = scale * sum_k A[m][k]*B[n][k], A=(Ah+Al), B=(Bh+Bl), K-major.
// Tile 128 x BN, BK=32, 256 threads, warp grid 2(m) x 4(n).
// flags: 1=+bias, 2=gelu, 4=+residual(fp32), 8=dual bf16 out (else fp32 out)
template <int BN>
__global__ void __launch_bounds__(256)
bf_gemm(const bf16* __restrict__ Ah, const bf16* __restrict__ Al,
        const bf16* __restrict__ Bh, const bf16* __restrict__ Bl,
        const float* __restrict__ bias, const float* __restrict__ res,
        float* __restrict__ Cf, bf16* __restrict__ Oh, bf16* __restrict__ Ol,
        int K, TLL lda, TLL ldb, TLL ldc,
        TLL bsA, TLL hsA, TLL bsB, TLL hsB, TLL bsC, TLL hsC,
        int nH, float scale, int flags) {
    constexpr int RS = 40;                        // bf16 per smem row (80B, 16B-aligned)
    constexpr int A_ELEMS = 128 * RS;             // 5120
    constexpr int B_ELEMS = BN * RS;
    constexpr int BUF = 2 * A_ELEMS + 2 * B_ELEMS;
    constexpr int WTN = BN / 4;
    constexpr int NI  = WTN / 8;

    extern __shared__ __align__(16) bf16 dynsm[];
    const uint32_t sb = smem_u32(dynsm);

    const int tid = threadIdx.x, lane = tid & 31, wid = tid >> 5;
    const int wm = wid & 1, wn = wid >> 1;

    const int z = blockIdx.z, bz = z / nH, hz = z - bz * nH;
    Ah += (TLL)bz * bsA + (TLL)hz * hsA;  Al += (TLL)bz * bsA + (TLL)hz * hsA;
    Bh += (TLL)bz * bsB + (TLL)hz * hsB;  Bl += (TLL)bz * bsB + (TLL)hz * hsB;
    const TLL cOff = (TLL)bz * bsC + (TLL)hz * hsC;

    const TLL rowBase = (TLL)blockIdx.y * 128;
    const TLL colBase = (TLL)blockIdx.x * BN;

    float acc[4][NI][4];
#pragma unroll
    for (int i = 0; i < 4; i++)
#pragma unroll
        for (int j = 0; j < NI; j++)
#pragma unroll
            for (int q = 0; q < 4; q++) acc[i][j][q] = 0.f;

    auto stage = [&](int buf, int k0) {
        const uint32_t bb = sb + buf * (BUF * 2);
        // A: 2 arrays x 128 rows x 4 chunks(16B) = 1024 chunks
#pragma unroll
        for (int t = 0; t < 4; t++) {
            int idx = tid + (t << 8);
            int arr = idx >> 9, i2 = idx & 511;
            int r = i2 >> 2, c = i2 & 3;
            const bf16* g = (arr ? Al : Ah) + (rowBase + r) * lda + (k0 + c * 8);
            uint32_t d = bb + (arr * A_ELEMS + r * RS + c * 8) * 2;
            CP16(d, g);
        }
        // B: 2 arrays x BN rows x 4 chunks
#pragma unroll
        for (int t = 0; t < BN / 32; t++) {
            int idx = tid + (t << 8);
            int arr = idx / (BN * 4), i2 = idx % (BN * 4);
            int r = i2 >> 2, c = i2 & 3;
            const bf16* g = (arr ? Bl : Bh) + (colBase + r) * ldb + (k0 + c * 8);
            uint32_t d = bb + (2 * A_ELEMS + arr * B_ELEMS + r * RS + c * 8) * 2;
            CP16(d, g);
        }
        asm volatile("cp.async.commit_group;");
    };

    const int iters = K / 32;
    int buf = 0;
    stage(0, 0);

    for (int it = 0; it < iters; ++it) {
        if (it + 1 < iters) {
            stage(buf ^ 1, (it + 1) * 32);
            asm volatile("cp.async.wait_group 1;" ::: "memory");
        } else {
            asm volatile("cp.async.wait_group 0;" ::: "memory");
        }
        __syncthreads();

        const uint32_t bb = sb + buf * (BUF * 2);
        const uint32_t aRow = (wm * 64 + (lane & 15)) * RS * 2 + ((lane >> 4) << 4);
        const uint32_t bRow = (wn * WTN + (lane & 7)) * RS * 2 + (((lane >> 3) & 1) << 4);

#pragma unroll
        for (int ks = 0; ks < 2; ks++) {
            uint32_t bh[NI][2], bl[NI][2];
#pragma unroll
            for (int ni = 0; ni < NI; ni++) {
                uint32_t ba = bb + 2 * A_ELEMS * 2 + bRow + ni * (8 * RS * 2) + ks * 32;
                LDSM2(bh[ni], ba);
                LDSM2(bl[ni], ba + B_ELEMS * 2);
            }
#pragma unroll
            for (int mi = 0; mi < 4; mi++) {
                uint32_t aa = bb + aRow + mi * (16 * RS * 2) + ks * 32;
                uint32_t ah[4], al[4];
                LDSM4(ah, aa);
                LDSM4(al, aa + A_ELEMS * 2);
#pragma unroll
                for (int ni = 0; ni < NI; ni++) {
                    mma_bf16(acc[mi][ni], al, bh[ni]);
                    mma_bf16(acc[mi][ni], ah, bl[ni]);
                    mma_bf16(acc[mi][ni], ah, bh[ni]);
                }
            }
        }
        __syncthreads();
        buf ^= 1;
    }

    // ---------------- epilogue ----------------
    const int lq = lane >> 2, lr = lane & 3;
#pragma unroll
    for (int mi = 0; mi < 4; mi++) {
        TLL r0 = rowBase + wm * 64 + mi * 16 + lq;
#pragma unroll
        for (int ni = 0; ni < NI; ni++) {
            TLL c = colBase + wn * WTN + ni * 8 + 2 * lr;
            float v00 = acc[mi][ni][0] * scale, v01 = acc[mi][ni][1] * scale;
            float v10 = acc[mi][ni][2] * scale, v11 = acc[mi][ni][3] * scale;
            if (flags & 1) {
                float b0 = bias[c], b1 = bias[c + 1];
                v00 += b0; v01 += b1; v10 += b0; v11 += b1;
            }
            if (flags & 2) {
                v00 = gelu_f(v00); v01 = gelu_f(v01);
                v10 = gelu_f(v10); v11 = gelu_f(v11);
            }
            if (flags & 4) {
                const float* R = res + cOff;
                float2 ra = *(const float2*)(R + r0 * ldc + c);
                float2 rb = *(const float2*)(R + (r0 + 8) * ldc + c);
                v00 += ra.x; v01 += ra.y; v10 += rb.x; v11 += rb.y;
            }
            if (flags & 8) {
                bf16 h0, l0, h1, l1;
                __nv_bfloat162 ph, pl;
                split_bf(v00, h0, l0); split_bf(v01, h1, l1);
                ph.x = h0; ph.y = h1; pl.x = l0; pl.y = l1;
                *(__nv_bfloat162*)(Oh + cOff + r0 * ldc + c) = ph;
                *(__nv_bfloat162*)(Ol + cOff + r0 * ldc + c) = pl;
                split_bf(v10, h0, l0); split_bf(v11, h1, l1);
                ph.x = h0; ph.y = h1; pl.x = l0; pl.y = l1;
                *(__nv_bfloat162*)(Oh + cOff + (r0 + 8) * ldc + c) = ph;
                *(__nv_bfloat162*)(Ol + cOff + (r0 + 8) * ldc + c) = pl;
            } else {
                float* C = Cf + cOff;
                *(float2*)(C + r0 * ldc + c) = make_float2(v00, v01);
                *(float2*)(C + (r0 + 8) * ldc + c) = make_float2(v10, v11);
            }
        }
    }
}

// ---------------- launch ----------------
extern "C" void kernel_launch(void* const* d_in, const int* in_sizes, int n_in,
                              void* d_out, int out_size) {
    const float* x          = (const float*)d_in[0];
    const float* ln1_g      = (const float*)d_in[1];
    const float* ln1_b      = (const float*)d_in[2];
    const float* w_qkv      = (const float*)d_in[3];
    const float* b_qkv      = (const float*)d_in[4];
    const float* w_attnproj = (const float*)d_in[5];
    const float* b_attnproj = (const float*)d_in[6];
    const float* ln2_g      = (const float*)d_in[7];
    const float* ln2_b      = (const float*)d_in[8];
    const float* w_fc       = (const float*)d_in[9];
    const float* b_fc       = (const float*)d_in[10];
    const float* w_proj     = (const float*)d_in[11];
    const float* b_proj     = (const float*)d_in[12];
    float* out = (float*)d_out;

    float *S, *x1;
    bf16 *h_hi, *h_lo, *qkv_hi, *qkv_lo, *P_hi, *P_lo, *vT_hi, *vT_lo;
    bf16 *y_hi, *y_lo, *h2_hi, *h2_lo, *ff_hi, *ff_lo;
    bf16 *wqkvT_hi, *wqkvT_lo, *wapT_hi, *wapT_lo, *wfcT_hi, *wfcT_lo, *wprjT_hi, *wprjT_lo;
    cudaGetSymbolAddress((void**)&S,    g_S);
    cudaGetSymbolAddress((void**)&x1,   g_x1);
    cudaGetSymbolAddress((void**)&h_hi, g_h_hi);   cudaGetSymbolAddress((void**)&h_lo, g_h_lo);
    cudaGetSymbolAddress((void**)&qkv_hi, g_qkv_hi); cudaGetSymbolAddress((void**)&qkv_lo, g_qkv_lo);
    cudaGetSymbolAddress((void**)&P_hi, g_P_hi);   cudaGetSymbolAddress((void**)&P_lo, g_P_lo);
    cudaGetSymbolAddress((void**)&vT_hi, g_vT_hi); cudaGetSymbolAddress((void**)&vT_lo, g_vT_lo);
    cudaGetSymbolAddress((void**)&y_hi, g_y_hi);   cudaGetSymbolAddress((void**)&y_lo, g_y_lo);
    cudaGetSymbolAddress((void**)&h2_hi, g_h2_hi); cudaGetSymbolAddress((void**)&h2_lo, g_h2_lo);
    cudaGetSymbolAddress((void**)&ff_hi, g_ff_hi); cudaGetSymbolAddress((void**)&ff_lo, g_ff_lo);
    cudaGetSymbolAddress((void**)&wqkvT_hi, g_wqkvT_hi); cudaGetSymbolAddress((void**)&wqkvT_lo, g_wqkvT_lo);
    cudaGetSymbolAddress((void**)&wapT_hi, g_wapT_hi);   cudaGetSymbolAddress((void**)&wapT_lo, g_wapT_lo);
    cudaGetSymbolAddress((void**)&wfcT_hi, g_wfcT_hi);   cudaGetSymbolAddress((void**)&wfcT_lo, g_wfcT_lo);
    cudaGetSymbolAddress((void**)&wprjT_hi, g_wprjT_hi); cudaGetSymbolAddress((void**)&wprjT_lo, g_wprjT_lo);

    static bool attr_done = false;
    if (!attr_done) {
        cudaFuncSetAttribute(bf_gemm<128>, cudaFuncAttributeMaxDynamicSharedMemorySize, 81920);
        cudaFuncSetAttribute(bf_gemm<64>,  cudaFuncAttributeMaxDynamicSharedMemorySize, 61440);
        attr_done = true;
    }
    const int SM128 = 81920, SM64 = 61440;

    dim3 tb(32, 8);
    // weight transposes + dual conversion ([K,N] -> [N,K])
    transpose_conv<<<dim3(3 * CC / 32, CC / 32), tb>>>(w_qkv, wqkvT_hi, wqkvT_lo, 3 * CC, CC);
    transpose_conv<<<dim3(CC / 32, CC / 32), tb>>>(w_attnproj, wapT_hi, wapT_lo, CC, CC);
    transpose_conv<<<dim3(DFF / 32, CC / 32), tb>>>(w_fc, wfcT_hi, wfcT_lo, DFF, CC);
    transpose_conv<<<dim3(CC / 32, DFF / 32), tb>>>(w_proj, wprjT_hi, wprjT_lo, CC, DFF);

    // 1) h = LN1(x)  (dual)
    ln_dual<<<ROWS, 256>>>(x, ln1_g, ln1_b, h_hi, h_lo);

    // 2) qkv = h @ w_qkv + b_qkv  (dual out)
    bf_gemm<128><<<dim3(3 * CC / 128, ROWS / 128, 1), 256, SM128>>>(
        h_hi, h_lo, wqkvT_hi, wqkvT_lo, b_qkv, nullptr,
        nullptr, qkv_hi, qkv_lo, CC,
        CC, CC, 3 * CC, 0, 0, 0, 0, 0, 0, 1, 1.0f, 1 | 8);

    // 3) S = Q @ K^T / 8  (fp32 out, batched 64)
    bf_gemm<128><<<dim3(TT / 128, TT / 128, BB * HH), 256, SM128>>>(
        qkv_hi, qkv_lo, qkv_hi + CC, qkv_lo + CC, nullptr, nullptr,
        S, nullptr, nullptr, HD,
        3 * CC, 3 * CC, TT,
        (TLL)TT * 3 * CC, HD, (TLL)TT * 3 * CC, HD,
        (TLL)HH * TT * TT, (TLL)TT * TT, HH, 0.125f, 0);

    // 4) softmax -> P dual
    softmax_dual<<<BB * HH * TT, 256>>>(S, P_hi, P_lo);

    // 5) vT = V^T per (b,h)
    transpose_dual<<<dim3(HD / 32, TT / 32, BB * HH), tb>>>(
        qkv_hi + 2 * CC, qkv_lo + 2 * CC, vT_hi, vT_lo,
        3 * CC, TT, (TLL)TT * 3 * CC, HD, (TLL)HD * TT, HH);

    // 6) y = P @ V  (dual out, batched 64, N=64)
    bf_gemm<64><<<dim3(1, TT / 128, BB * HH), 256, SM64>>>(
        P_hi, P_lo, vT_hi, vT_lo, nullptr, nullptr,
        nullptr, y_hi, y_lo, TT,
        TT, TT, CC,
        (TLL)HH * TT * TT, (TLL)TT * TT,
        (TLL)HH * HD * TT, (TLL)HD * TT,
        (TLL)TT * CC, HD, HH, 1.0f, 8);

    // 7) x1 = x + y @ w_attnproj + b  (fp32 out)
    bf_gemm<128><<<dim3(CC / 128, ROWS / 128, 1), 256, SM128>>>(
        y_hi, y_lo, wapT_hi, wapT_lo, b_attnproj, x,
        x1, nullptr, nullptr, CC,
        CC, CC, CC, 0, 0, 0, 0, 0, 0, 1, 1.0f, 1 | 4);

    // 8) h2 = LN2(x1)  (dual)
    ln_dual<<<ROWS, 256>>>(x1, ln2_g, ln2_b, h2_hi, h2_lo);

    // 9) ff = gelu(h2 @ w_fc + b_fc)  (dual out)
    bf_gemm<128><<<dim3(DFF / 128, ROWS / 128, 1), 256, SM128>>>(
        h2_hi, h2_lo, wfcT_hi, wfcT_lo, b_fc, nullptr,
        nullptr, ff_hi, ff_lo, CC,
        CC, CC, DFF, 0, 0, 0, 0, 0, 0, 1, 1.0f, 1 | 2 | 8);

    // 10) out = x1 + ff @ w_proj + b_proj  (fp32 out)
    bf_gemm<128><<<dim3(CC / 128, ROWS / 128, 1), 256, SM128>>>(
        ff_hi, ff_lo, wprjT_hi, wprjT_lo, b_proj, x1,
        out, nullptr, nullptr, DFF,
        DFF, DFF, CC, 0, 0, 0, 0, 0, 0, 1, 1.0f, 1 | 4);
}

// round 6
// speedup vs baseline: 3.9278x; 1.3868x over previous
#include <cuda_runtime.h>
#include <cuda_bf16.h>
#include <math.h>
#include <stdint.h>

typedef long long TLL;
typedef __nv_bfloat16 bf16;

// ---------------- problem constants ----------------
#define BB   4
#define TT   2048
#define CC   1024
#define HH   16
#define HD   64
#define DFF  4096
#define ROWS (BB*TT)          // 8192

// ---------------- scratch ----------------
__device__ float g_x1  [(TLL)ROWS*CC];          // residual 1 (fp32)

__device__ bf16 g_h_hi [(TLL)ROWS*CC],      g_h_lo [(TLL)ROWS*CC];
__device__ bf16 g_qkv_hi[(TLL)ROWS*3*CC];
__device__ bf16 g_y_hi [(TLL)ROWS*CC],      g_y_lo [(TLL)ROWS*CC];
__device__ bf16 g_h2_hi[(TLL)ROWS*CC],      g_h2_lo[(TLL)ROWS*CC];
__device__ bf16 g_ff_hi[(TLL)ROWS*DFF],     g_ff_lo[(TLL)ROWS*DFF];
__device__ bf16 g_wqkvT_hi[(TLL)3*CC*CC],   g_wqkvT_lo[(TLL)3*CC*CC];
__device__ bf16 g_wapT_hi [(TLL)CC*CC],     g_wapT_lo [(TLL)CC*CC];
__device__ bf16 g_wfcT_hi [(TLL)DFF*CC],    g_wfcT_lo [(TLL)DFF*CC];
__device__ bf16 g_wprjT_hi[(TLL)CC*DFF],    g_wprjT_lo[(TLL)CC*DFF];

// ---------------- helpers ----------------
__device__ __forceinline__ uint32_t smem_u32(const void* p) {
    return (uint32_t)__cvta_generic_to_shared(p);
}
__device__ __forceinline__ float gelu_f(float x) {
    const float c = 0.7978845608028654f;
    float t = tanhf(c * (x + 0.044715f * x * x * x));
    return 0.5f * x * (1.0f + t);
}
__device__ __forceinline__ float ex2f(float x) {
    float y; asm("ex2.approx.f32 %0, %1;" : "=f"(y) : "f"(x)); return y;
}
__device__ __forceinline__ void split_bf(float v, bf16& h, bf16& l) {
    h = __float2bfloat16(v);
    l = __float2bfloat16(v - __bfloat162float(h));
}
__device__ __forceinline__ void mma_bf16(float* d, const uint32_t* a, const uint32_t* b) {
    asm volatile(
        "mma.sync.aligned.m16n8k16.row.col.f32.bf16.bf16.f32 "
        "{%0,%1,%2,%3}, {%4,%5,%6,%7}, {%8,%9}, {%0,%1,%2,%3};"
        : "+f"(d[0]), "+f"(d[1]), "+f"(d[2]), "+f"(d[3])
        : "r"(a[0]), "r"(a[1]), "r"(a[2]), "r"(a[3]), "r"(b[0]), "r"(b[1]));
}
#define LDSM4(r, addr) \
    asm volatile("ldmatrix.sync.aligned.m8n8.x4.shared.b16 {%0,%1,%2,%3}, [%4];" \
        : "=r"((r)[0]), "=r"((r)[1]), "=r"((r)[2]), "=r"((r)[3]) : "r"(addr))
#define LDSM4T(r, addr) \
    asm volatile("ldmatrix.sync.aligned.m8n8.x4.trans.shared.b16 {%0,%1,%2,%3}, [%4];" \
        : "=r"((r)[0]), "=r"((r)[1]), "=r"((r)[2]), "=r"((r)[3]) : "r"(addr))
#define LDSM2(r, addr) \
    asm volatile("ldmatrix.sync.aligned.m8n8.x2.shared.b16 {%0,%1}, [%2];" \
        : "=r"((r)[0]), "=r"((r)[1]) : "r"(addr))
#define CP16(dst, src) \
    asm volatile("cp.async.cg.shared.global [%0], [%1], 16;" :: "r"(dst), "l"(src))

// ---------------- LayerNorm -> dual bf16 ----------------
__global__ void ln_dual(const float* __restrict__ x,
                        const float* __restrict__ g,
                        const float* __restrict__ b,
                        bf16* __restrict__ oh, bf16* __restrict__ ol) {
    const int row = blockIdx.x;
    const float* xr = x + (TLL)row * CC;
    float v[4]; float s = 0.f, ss = 0.f;
#pragma unroll
    for (int i = 0; i < 4; i++) {
        v[i] = xr[threadIdx.x + 256 * i];
        s += v[i]; ss += v[i] * v[i];
    }
#pragma unroll
    for (int o = 16; o; o >>= 1) {
        s  += __shfl_xor_sync(0xffffffffu, s, o);
        ss += __shfl_xor_sync(0xffffffffu, ss, o);
    }
    __shared__ float sh0[8], sh1[8];
    int w = threadIdx.x >> 5, l = threadIdx.x & 31;
    if (!l) { sh0[w] = s; sh1[w] = ss; }
    __syncthreads();
    if (threadIdx.x == 0) {
        float S = 0.f, SS = 0.f;
#pragma unroll
        for (int i = 0; i < 8; i++) { S += sh0[i]; SS += sh1[i]; }
        float mu = S * (1.0f / CC);
        float var = SS * (1.0f / CC) - mu * mu;
        sh0[0] = mu; sh1[0] = rsqrtf(var + 1e-5f);
    }
    __syncthreads();
    float mu = sh0[0], rstd = sh1[0];
#pragma unroll
    for (int i = 0; i < 4; i++) {
        int c = threadIdx.x + 256 * i;
        float o = (v[i] - mu) * rstd * g[c] + b[c];
        bf16 hi, lo; split_bf(o, hi, lo);
        oh[(TLL)row * CC + c] = hi;
        ol[(TLL)row * CC + c] = lo;
    }
}

// ---------------- transpose fp32 -> dual bf16 ([K,N] -> [N,K]) -------------
__global__ void transpose_conv(const float* __restrict__ in,
                               bf16* __restrict__ oh, bf16* __restrict__ ol,
                               int ldin, int ldout) {
    __shared__ float t[32][33];
    int k0 = blockIdx.y * 32, n0 = blockIdx.x * 32;
    int tx = threadIdx.x, ty = threadIdx.y;
#pragma unroll
    for (int i = 0; i < 32; i += 8)
        t[ty + i][tx] = in[(TLL)(k0 + ty + i) * ldin + (n0 + tx)];
    __syncthreads();
#pragma unroll
    for (int i = 0; i < 32; i += 8) {
        bf16 hi, lo; split_bf(t[tx][ty + i], hi, lo);
        TLL o = (TLL)(n0 + ty + i) * ldout + (k0 + tx);
        oh[o] = hi; ol[o] = lo;
    }
}

// ---------------- fused flash attention -----------------------------------
// grid (16, 1, 64): z = b*16 + h, x = 128-row Q block. 256 threads, 8 warps,
// each warp owns 16 Q rows. K/V tiles 128x64, double buffered.
__global__ void __launch_bounds__(256)
flash_attn(const bf16* __restrict__ qkv,
           bf16* __restrict__ yh, bf16* __restrict__ yl) {
    constexpr int RS = 72;                     // bf16 per smem row
    constexpr int TILE = 128 * RS * 2;         // bytes per 128x64 tile
    extern __shared__ __align__(16) bf16 fsm[];
    const uint32_t sQ  = smem_u32(fsm);
    const uint32_t sKV = sQ + TILE;            // buf b: K at b*2*TILE, V at +TILE

    const int tid = threadIdx.x, lane = tid & 31, wid = tid >> 5;
    const int lq = lane >> 2, lr = lane & 3;
    const int z = blockIdx.z, bz = z >> 4, hz = z & 15;
    const int t0 = blockIdx.x * 128;

    const bf16* Qg = qkv + ((TLL)bz * TT + t0) * (3 * CC) + hz * HD;
    const bf16* Kg = qkv + ((TLL)bz * TT) * (3 * CC) + CC + hz * HD;
    const bf16* Vg = Kg + CC;

    // stage Q (one group)
#pragma unroll
    for (int t = 0; t < 4; t++) {
        int idx = tid + (t << 8);
        int r = idx >> 3, c = idx & 7;
        CP16(sQ + (r * RS + c * 8) * 2, Qg + (TLL)r * (3 * CC) + c * 8);
    }
    asm volatile("cp.async.commit_group;");

    auto stageKV = [&](int buf, int s0) {
        uint32_t base = sKV + buf * (2 * TILE);
#pragma unroll
        for (int t = 0; t < 4; t++) {
            int idx = tid + (t << 8);
            int r = idx >> 3, c = idx & 7;
            CP16(base + (r * RS + c * 8) * 2, Kg + (TLL)(s0 + r) * (3 * CC) + c * 8);
            CP16(base + TILE + (r * RS + c * 8) * 2, Vg + (TLL)(s0 + r) * (3 * CC) + c * 8);
        }
        asm volatile("cp.async.commit_group;");
    };
    stageKV(0, 0);

    uint32_t qf[4][4];
    float y[8][4];
    float m_lo = -1e30f, m_hi = -1e30f, l_lo = 0.f, l_hi = 0.f;
#pragma unroll
    for (int i = 0; i < 8; i++)
#pragma unroll
        for (int q = 0; q < 4; q++) y[i][q] = 0.f;

    const float c_s = 0.125f * 1.4426950408889634f;   // 1/sqrt(64) * log2(e)

    for (int it = 0; it < TT / 128; ++it) {
        if (it + 1 < TT / 128) {
            stageKV((it + 1) & 1, (it + 1) * 128);
            asm volatile("cp.async.wait_group 1;" ::: "memory");
        } else {
            asm volatile("cp.async.wait_group 0;" ::: "memory");
        }
        __syncthreads();

        if (it == 0) {   // load Q fragments once
#pragma unroll
            for (int c = 0; c < 4; c++) {
                uint32_t a = sQ + (((wid * 16) + (lane & 15)) * RS
                                   + c * 16 + ((lane >> 4) & 1) * 8) * 2;
                LDSM4(qf[c], a);
            }
        }

        const uint32_t bbK = sKV + (it & 1) * (2 * TILE);
        const uint32_t bbV = bbK + TILE;

        // ---- S = Q K^T (scaled to log2 space) ----
        float S[16][4];
#pragma unroll
        for (int nt = 0; nt < 16; nt++) {
            S[nt][0] = S[nt][1] = S[nt][2] = S[nt][3] = 0.f;
            uint32_t b0[4], b1[4];
            uint32_t a0 = bbK + ((nt * 8 + (lane & 7)) * RS + ((lane >> 3) & 3) * 8) * 2;
            LDSM4(b0, a0);
            LDSM4(b1, a0 + 64);
            mma_bf16(S[nt], qf[0], b0);
            mma_bf16(S[nt], qf[1], b0 + 2);
            mma_bf16(S[nt], qf[2], b1);
            mma_bf16(S[nt], qf[3], b1 + 2);
        }

        // ---- online softmax ----
        float mx0 = -1e30f, mx1 = -1e30f;
#pragma unroll
        for (int nt = 0; nt < 16; nt++) {
            S[nt][0] *= c_s; S[nt][1] *= c_s; S[nt][2] *= c_s; S[nt][3] *= c_s;
            mx0 = fmaxf(mx0, fmaxf(S[nt][0], S[nt][1]));
            mx1 = fmaxf(mx1, fmaxf(S[nt][2], S[nt][3]));
        }
        mx0 = fmaxf(mx0, __shfl_xor_sync(0xffffffffu, mx0, 1));
        mx0 = fmaxf(mx0, __shfl_xor_sync(0xffffffffu, mx0, 2));
        mx1 = fmaxf(mx1, __shfl_xor_sync(0xffffffffu, mx1, 1));
        mx1 = fmaxf(mx1, __shfl_xor_sync(0xffffffffu, mx1, 2));
        float nmlo = fmaxf(m_lo, mx0), nmhi = fmaxf(m_hi, mx1);
        float al = ex2f(m_lo - nmlo), ah = ex2f(m_hi - nmhi);
        m_lo = nmlo; m_hi = nmhi;
        l_lo *= al; l_hi *= ah;
#pragma unroll
        for (int i = 0; i < 8; i++) {
            y[i][0] *= al; y[i][1] *= al; y[i][2] *= ah; y[i][3] *= ah;
        }

        uint32_t pa[8][4];
#pragma unroll
        for (int kc = 0; kc < 8; kc++) {
#pragma unroll
            for (int half = 0; half < 2; half++) {
                int nt = 2 * kc + half;
                float p0 = ex2f(S[nt][0] - m_lo);
                float p1 = ex2f(S[nt][1] - m_lo);
                float p2 = ex2f(S[nt][2] - m_hi);
                float p3 = ex2f(S[nt][3] - m_hi);
                l_lo += p0 + p1; l_hi += p2 + p3;
                __nv_bfloat162 q01 = __floats2bfloat162_rn(p0, p1);
                __nv_bfloat162 q23 = __floats2bfloat162_rn(p2, p3);
                pa[kc][2 * half + 0] = *(uint32_t*)&q01;
                pa[kc][2 * half + 1] = *(uint32_t*)&q23;
            }
        }

        // ---- y += P V ----
#pragma unroll
        for (int kc = 0; kc < 8; kc++) {
#pragma unroll
            for (int np = 0; np < 4; np++) {
                uint32_t vf[4];
                uint32_t a = bbV + ((kc * 16 + ((lane >> 3) & 1) * 8 + (lane & 7)) * RS
                                    + np * 16 + ((lane >> 4) & 1) * 8) * 2;
                LDSM4T(vf, a);
                mma_bf16(y[2 * np], pa[kc], vf);
                mma_bf16(y[2 * np + 1], pa[kc], vf + 2);
            }
        }
        __syncthreads();
    }

    // ---- finalize: y /= l, write dual bf16 ----
    l_lo += __shfl_xor_sync(0xffffffffu, l_lo, 1);
    l_lo += __shfl_xor_sync(0xffffffffu, l_lo, 2);
    l_hi += __shfl_xor_sync(0xffffffffu, l_hi, 1);
    l_hi += __shfl_xor_sync(0xffffffffu, l_hi, 2);
    float inv_lo = 1.f / l_lo, inv_hi = 1.f / l_hi;

    TLL row_lo = (TLL)bz * TT + t0 + wid * 16 + lq;
    TLL row_hi = row_lo + 8;
#pragma unroll
    for (int nt = 0; nt < 8; nt++) {
        int col = hz * HD + nt * 8 + 2 * lr;
        float v0 = y[nt][0] * inv_lo, v1 = y[nt][1] * inv_lo;
        float v2 = y[nt][2] * inv_hi, v3 = y[nt][3] * inv_hi;
        bf16 h0, l0, h1, l1;
        __nv_bfloat162 ph, pl;
        split_bf(v0, h0, l0); split_bf(v1, h1, l1);
        ph.x = h0; ph.y = h1; pl.x = l0; pl.y = l1;
        *(__nv_bfloat162*)(yh + row_lo * CC + col) = ph;
        *(__nv_bfloat162*)(yl + row_lo * CC + col) = pl;
        split_bf(v2, h0, l0); split_bf(v3, h1, l1);
        ph.x = h0; ph.y = h1; pl.x = l0; pl.y = l1;
        *(__nv_bfloat162*)(yh + row_hi * CC + col) = ph;
        *(__nv_bfloat162*)(yl + row_hi * CC + col) = pl;
    }
}

// ---------------- bf16x3 mma.sync GEMM -------------------------------------
// D[m][n] = scale * sum_k A[m][k]*B[n][k], A=(Ah+Al), B=(Bh+Bl), K-major.
// Tile 128 x BN, BK=32, 256 threads, warp grid 2(m) x 4(n).
// flags: 1=+bias, 2=gelu, 4=+residual(fp32), 8=dual bf16 out, 16=hi-only bf16 out
template <int BN>
__global__ void __launch_bounds__(256)
bf_gemm(const bf16* __restrict__ Ah, const bf16* __restrict__ Al,
        const bf16* __restrict__ Bh, const bf16* __restrict__ Bl,
        const float* __restrict__ bias, const float* __restrict__ res,
        float* __restrict__ Cf, bf16* __restrict__ Oh, bf16* __restrict__ Ol,
        int K, TLL lda, TLL ldb, TLL ldc,
        float scale, int flags) {
    constexpr int RS = 40;
    constexpr int A_ELEMS = 128 * RS;
    constexpr int B_ELEMS = BN * RS;
    constexpr int BUF = 2 * A_ELEMS + 2 * B_ELEMS;
    constexpr int WTN = BN / 4;
    constexpr int NI  = WTN / 8;

    extern __shared__ __align__(16) bf16 dynsm[];
    const uint32_t sb = smem_u32(dynsm);

    const int tid = threadIdx.x, lane = tid & 31, wid = tid >> 5;
    const int wm = wid & 1, wn = wid >> 1;

    const TLL rowBase = (TLL)blockIdx.y * 128;
    const TLL colBase = (TLL)blockIdx.x * BN;

    float acc[4][NI][4];
#pragma unroll
    for (int i = 0; i < 4; i++)
#pragma unroll
        for (int j = 0; j < NI; j++)
#pragma unroll
            for (int q = 0; q < 4; q++) acc[i][j][q] = 0.f;

    auto stage = [&](int buf, int k0) {
        const uint32_t bb = sb + buf * (BUF * 2);
#pragma unroll
        for (int t = 0; t < 4; t++) {
            int idx = tid + (t << 8);
            int arr = idx >> 9, i2 = idx & 511;
            int r = i2 >> 2, c = i2 & 3;
            const bf16* g = (arr ? Al : Ah) + (rowBase + r) * lda + (k0 + c * 8);
            uint32_t d = bb + (arr * A_ELEMS + r * RS + c * 8) * 2;
            CP16(d, g);
        }
#pragma unroll
        for (int t = 0; t < BN / 32; t++) {
            int idx = tid + (t << 8);
            int arr = idx / (BN * 4), i2 = idx % (BN * 4);
            int r = i2 >> 2, c = i2 & 3;
            const bf16* g = (arr ? Bl : Bh) + (colBase + r) * ldb + (k0 + c * 8);
            uint32_t d = bb + (2 * A_ELEMS + arr * B_ELEMS + r * RS + c * 8) * 2;
            CP16(d, g);
        }
        asm volatile("cp.async.commit_group;");
    };

    const int iters = K / 32;
    int buf = 0;
    stage(0, 0);

    for (int it = 0; it < iters; ++it) {
        if (it + 1 < iters) {
            stage(buf ^ 1, (it + 1) * 32);
            asm volatile("cp.async.wait_group 1;" ::: "memory");
        } else {
            asm volatile("cp.async.wait_group 0;" ::: "memory");
        }
        __syncthreads();

        const uint32_t bb = sb + buf * (BUF * 2);
        const uint32_t aRow = (wm * 64 + (lane & 15)) * RS * 2 + ((lane >> 4) << 4);
        const uint32_t bRow = (wn * WTN + (lane & 7)) * RS * 2 + (((lane >> 3) & 1) << 4);

#pragma unroll
        for (int ks = 0; ks < 2; ks++) {
            uint32_t bh[NI][2], bl[NI][2];
#pragma unroll
            for (int ni = 0; ni < NI; ni++) {
                uint32_t ba = bb + 2 * A_ELEMS * 2 + bRow + ni * (8 * RS * 2) + ks * 32;
                LDSM2(bh[ni], ba);
                LDSM2(bl[ni], ba + B_ELEMS * 2);
            }
#pragma unroll
            for (int mi = 0; mi < 4; mi++) {
                uint32_t aa = bb + aRow + mi * (16 * RS * 2) + ks * 32;
                uint32_t ah[4], al[4];
                LDSM4(ah, aa);
                LDSM4(al, aa + A_ELEMS * 2);
#pragma unroll
                for (int ni = 0; ni < NI; ni++) {
                    mma_bf16(acc[mi][ni], al, bh[ni]);
                    mma_bf16(acc[mi][ni], ah, bl[ni]);
                    mma_bf16(acc[mi][ni], ah, bh[ni]);
                }
            }
        }
        __syncthreads();
        buf ^= 1;
    }

    const int lq = lane >> 2, lr = lane & 3;
#pragma unroll
    for (int mi = 0; mi < 4; mi++) {
        TLL r0 = rowBase + wm * 64 + mi * 16 + lq;
#pragma unroll
        for (int ni = 0; ni < NI; ni++) {
            TLL c = colBase + wn * WTN + ni * 8 + 2 * lr;
            float v00 = acc[mi][ni][0] * scale, v01 = acc[mi][ni][1] * scale;
            float v10 = acc[mi][ni][2] * scale, v11 = acc[mi][ni][3] * scale;
            if (flags & 1) {
                float b0 = bias[c], b1 = bias[c + 1];
                v00 += b0; v01 += b1; v10 += b0; v11 += b1;
            }
            if (flags & 2) {
                v00 = gelu_f(v00); v01 = gelu_f(v01);
                v10 = gelu_f(v10); v11 = gelu_f(v11);
            }
            if (flags & 4) {
                float2 ra = *(const float2*)(res + r0 * ldc + c);
                float2 rb = *(const float2*)(res + (r0 + 8) * ldc + c);
                v00 += ra.x; v01 += ra.y; v10 += rb.x; v11 += rb.y;
            }
            if (flags & 8) {
                bf16 h0, l0, h1, l1;
                __nv_bfloat162 ph, pl;
                split_bf(v00, h0, l0); split_bf(v01, h1, l1);
                ph.x = h0; ph.y = h1; pl.x = l0; pl.y = l1;
                *(__nv_bfloat162*)(Oh + r0 * ldc + c) = ph;
                *(__nv_bfloat162*)(Ol + r0 * ldc + c) = pl;
                split_bf(v10, h0, l0); split_bf(v11, h1, l1);
                ph.x = h0; ph.y = h1; pl.x = l0; pl.y = l1;
                *(__nv_bfloat162*)(Oh + (r0 + 8) * ldc + c) = ph;
                *(__nv_bfloat162*)(Ol + (r0 + 8) * ldc + c) = pl;
            } else if (flags & 16) {
                __nv_bfloat162 ph;
                ph.x = __float2bfloat16(v00); ph.y = __float2bfloat16(v01);
                *(__nv_bfloat162*)(Oh + r0 * ldc + c) = ph;
                ph.x = __float2bfloat16(v10); ph.y = __float2bfloat16(v11);
                *(__nv_bfloat162*)(Oh + (r0 + 8) * ldc + c) = ph;
            } else {
                *(float2*)(Cf + r0 * ldc + c) = make_float2(v00, v01);
                *(float2*)(Cf + (r0 + 8) * ldc + c) = make_float2(v10, v11);
            }
        }
    }
}

// ---------------- launch ----------------
extern "C" void kernel_launch(void* const* d_in, const int* in_sizes, int n_in,
                              void* d_out, int out_size) {
    const float* x          = (const float*)d_in[0];
    const float* ln1_g      = (const float*)d_in[1];
    const float* ln1_b      = (const float*)d_in[2];
    const float* w_qkv      = (const float*)d_in[3];
    const float* b_qkv      = (const float*)d_in[4];
    const float* w_attnproj = (const float*)d_in[5];
    const float* b_attnproj = (const float*)d_in[6];
    const float* ln2_g      = (const float*)d_in[7];
    const float* ln2_b      = (const float*)d_in[8];
    const float* w_fc       = (const float*)d_in[9];
    const float* b_fc       = (const float*)d_in[10];
    const float* w_proj     = (const float*)d_in[11];
    const float* b_proj     = (const float*)d_in[12];
    float* out = (float*)d_out;

    float *x1;
    bf16 *h_hi, *h_lo, *qkv_hi, *y_hi, *y_lo, *h2_hi, *h2_lo, *ff_hi, *ff_lo;
    bf16 *wqkvT_hi, *wqkvT_lo, *wapT_hi, *wapT_lo, *wfcT_hi, *wfcT_lo, *wprjT_hi, *wprjT_lo;
    cudaGetSymbolAddress((void**)&x1,   g_x1);
    cudaGetSymbolAddress((void**)&h_hi, g_h_hi);   cudaGetSymbolAddress((void**)&h_lo, g_h_lo);
    cudaGetSymbolAddress((void**)&qkv_hi, g_qkv_hi);
    cudaGetSymbolAddress((void**)&y_hi, g_y_hi);   cudaGetSymbolAddress((void**)&y_lo, g_y_lo);
    cudaGetSymbolAddress((void**)&h2_hi, g_h2_hi); cudaGetSymbolAddress((void**)&h2_lo, g_h2_lo);
    cudaGetSymbolAddress((void**)&ff_hi, g_ff_hi); cudaGetSymbolAddress((void**)&ff_lo, g_ff_lo);
    cudaGetSymbolAddress((void**)&wqkvT_hi, g_wqkvT_hi); cudaGetSymbolAddress((void**)&wqkvT_lo, g_wqkvT_lo);
    cudaGetSymbolAddress((void**)&wapT_hi, g_wapT_hi);   cudaGetSymbolAddress((void**)&wapT_lo, g_wapT_lo);
    cudaGetSymbolAddress((void**)&wfcT_hi, g_wfcT_hi);   cudaGetSymbolAddress((void**)&wfcT_lo, g_wfcT_lo);
    cudaGetSymbolAddress((void**)&wprjT_hi, g_wprjT_hi); cudaGetSymbolAddress((void**)&wprjT_lo, g_wprjT_lo);

    static bool attr_done = false;
    if (!attr_done) {
        cudaFuncSetAttribute(bf_gemm<128>, cudaFuncAttributeMaxDynamicSharedMemorySize, 81920);
        cudaFuncSetAttribute(flash_attn,   cudaFuncAttributeMaxDynamicSharedMemorySize, 92160);
        attr_done = true;
    }
    const int SM128 = 81920, SMFA = 92160;

    dim3 tb(32, 8);
    transpose_conv<<<dim3(3 * CC / 32, CC / 32), tb>>>(w_qkv, wqkvT_hi, wqkvT_lo, 3 * CC, CC);
    transpose_conv<<<dim3(CC / 32, CC / 32), tb>>>(w_attnproj, wapT_hi, wapT_lo, CC, CC);
    transpose_conv<<<dim3(DFF / 32, CC / 32), tb>>>(w_fc, wfcT_hi, wfcT_lo, DFF, CC);
    transpose_conv<<<dim3(CC / 32, DFF / 32), tb>>>(w_proj, wprjT_hi, wprjT_lo, CC, DFF);

    // 1) h = LN1(x)  (dual)
    ln_dual<<<ROWS, 256>>>(x, ln1_g, ln1_b, h_hi, h_lo);

    // 2) qkv = h @ w_qkv + b_qkv  (hi-only bf16 out)
    bf_gemm<128><<<dim3(3 * CC / 128, ROWS / 128, 1), 256, SM128>>>(
        h_hi, h_lo, wqkvT_hi, wqkvT_lo, b_qkv, nullptr,
        nullptr, qkv_hi, nullptr, CC,
        CC, CC, 3 * CC, 1.0f, 1 | 16);

    // 3-6) fused attention: y = softmax(QK^T/8) V  (dual out)
    flash_attn<<<dim3(TT / 128, 1, BB * HH), 256, SMFA>>>(qkv_hi, y_hi, y_lo);

    // 7) x1 = x + y @ w_attnproj + b  (fp32 out)
    bf_gemm<128><<<dim3(CC / 128, ROWS / 128, 1), 256, SM128>>>(
        y_hi, y_lo, wapT_hi, wapT_lo, b_attnproj, x,
        x1, nullptr, nullptr, CC,
        CC, CC, CC, 1.0f, 1 | 4);

    // 8) h2 = LN2(x1)  (dual)
    ln_dual<<<ROWS, 256>>>(x1, ln2_g, ln2_b, h2_hi, h2_lo);

    // 9) ff = gelu(h2 @ w_fc + b_fc)  (dual out)
    bf_gemm<128><<<dim3(DFF / 128, ROWS / 128, 1), 256, SM128>>>(
        h2_hi, h2_lo, wfcT_hi, wfcT_lo, b_fc, nullptr,
        nullptr, ff_hi, ff_lo, CC,
        CC, CC, DFF, 1.0f, 1 | 2 | 8);

    // 10) out = x1 + ff @ w_proj + b_proj  (fp32 out)
    bf_gemm<128><<<dim3(CC / 128, ROWS / 128, 1), 256, SM128>>>(
        ff_hi, ff_lo, wprjT_hi, wprjT_lo, b_proj, x1,
        out, nullptr, nullptr, DFF,
        DFF, DFF, CC, 1.0f, 1 | 4);
}

// round 7
// speedup vs baseline: 4.7094x; 1.1990x over previous
#include <cuda_runtime.h>
#include <cuda_bf16.h>
#include <math.h>
#include <stdint.h>

typedef long long TLL;
typedef __nv_bfloat16 bf16;

// ---------------- problem constants ----------------
#define BB   4
#define TT   2048
#define CC   1024
#define HH   16
#define HD   64
#define DFF  4096
#define ROWS (BB*TT)          // 8192

// ---------------- scratch ----------------
__device__ float g_x1  [(TLL)ROWS*CC];          // residual 1 (fp32)

__device__ bf16 g_h_hi [(TLL)ROWS*CC];
__device__ bf16 g_qkv_hi[(TLL)ROWS*3*CC];
__device__ bf16 g_y_hi [(TLL)ROWS*CC];
__device__ bf16 g_h2_hi[(TLL)ROWS*CC],      g_h2_lo[(TLL)ROWS*CC];
__device__ bf16 g_ff_hi[(TLL)ROWS*DFF],     g_ff_lo[(TLL)ROWS*DFF];
__device__ bf16 g_wqkvT_hi[(TLL)3*CC*CC];
__device__ bf16 g_wapT_hi [(TLL)CC*CC];
__device__ bf16 g_wfcT_hi [(TLL)DFF*CC],    g_wfcT_lo [(TLL)DFF*CC];
__device__ bf16 g_wprjT_hi[(TLL)CC*DFF],    g_wprjT_lo[(TLL)CC*DFF];

// ---------------- helpers ----------------
__device__ __forceinline__ uint32_t smem_u32(const void* p) {
    return (uint32_t)__cvta_generic_to_shared(p);
}
__device__ __forceinline__ float tanh_ap(float x) {
    float y; asm("tanh.approx.f32 %0, %1;" : "=f"(y) : "f"(x)); return y;
}
__device__ __forceinline__ float gelu_f(float x) {
    const float c = 0.7978845608028654f;
    float t = tanh_ap(c * (x + 0.044715f * x * x * x));
    return 0.5f * x * (1.0f + t);
}
__device__ __forceinline__ float ex2f(float x) {
    float y; asm("ex2.approx.f32 %0, %1;" : "=f"(y) : "f"(x)); return y;
}
__device__ __forceinline__ void split_bf(float v, bf16& h, bf16& l) {
    h = __float2bfloat16(v);
    l = __float2bfloat16(v - __bfloat162float(h));
}
__device__ __forceinline__ void mma_bf16(float* d, const uint32_t* a, const uint32_t* b) {
    asm volatile(
        "mma.sync.aligned.m16n8k16.row.col.f32.bf16.bf16.f32 "
        "{%0,%1,%2,%3}, {%4,%5,%6,%7}, {%8,%9}, {%0,%1,%2,%3};"
        : "+f"(d[0]), "+f"(d[1]), "+f"(d[2]), "+f"(d[3])
        : "r"(a[0]), "r"(a[1]), "r"(a[2]), "r"(a[3]), "r"(b[0]), "r"(b[1]));
}
#define LDSM4(r, addr) \
    asm volatile("ldmatrix.sync.aligned.m8n8.x4.shared.b16 {%0,%1,%2,%3}, [%4];" \
        : "=r"((r)[0]), "=r"((r)[1]), "=r"((r)[2]), "=r"((r)[3]) : "r"(addr))
#define LDSM4T(r, addr) \
    asm volatile("ldmatrix.sync.aligned.m8n8.x4.trans.shared.b16 {%0,%1,%2,%3}, [%4];" \
        : "=r"((r)[0]), "=r"((r)[1]), "=r"((r)[2]), "=r"((r)[3]) : "r"(addr))
#define LDSM2(r, addr) \
    asm volatile("ldmatrix.sync.aligned.m8n8.x2.shared.b16 {%0,%1}, [%2];" \
        : "=r"((r)[0]), "=r"((r)[1]) : "r"(addr))
#define CP16(dst, src) \
    asm volatile("cp.async.cg.shared.global [%0], [%1], 16;" :: "r"(dst), "l"(src))

// ---------------- LayerNorm variants ----------------
template <bool DUAL>
__global__ void ln_kernel(const float* __restrict__ x,
                          const float* __restrict__ g,
                          const float* __restrict__ b,
                          bf16* __restrict__ oh, bf16* __restrict__ ol) {
    const int row = blockIdx.x;
    const float* xr = x + (TLL)row * CC;
    float v[4]; float s = 0.f, ss = 0.f;
#pragma unroll
    for (int i = 0; i < 4; i++) {
        v[i] = xr[threadIdx.x + 256 * i];
        s += v[i]; ss += v[i] * v[i];
    }
#pragma unroll
    for (int o = 16; o; o >>= 1) {
        s  += __shfl_xor_sync(0xffffffffu, s, o);
        ss += __shfl_xor_sync(0xffffffffu, ss, o);
    }
    __shared__ float sh0[8], sh1[8];
    int w = threadIdx.x >> 5, l = threadIdx.x & 31;
    if (!l) { sh0[w] = s; sh1[w] = ss; }
    __syncthreads();
    if (threadIdx.x == 0) {
        float S = 0.f, SS = 0.f;
#pragma unroll
        for (int i = 0; i < 8; i++) { S += sh0[i]; SS += sh1[i]; }
        float mu = S * (1.0f / CC);
        float var = SS * (1.0f / CC) - mu * mu;
        sh0[0] = mu; sh1[0] = rsqrtf(var + 1e-5f);
    }
    __syncthreads();
    float mu = sh0[0], rstd = sh1[0];
#pragma unroll
    for (int i = 0; i < 4; i++) {
        int c = threadIdx.x + 256 * i;
        float o = (v[i] - mu) * rstd * g[c] + b[c];
        if (DUAL) {
            bf16 hi, lo; split_bf(o, hi, lo);
            oh[(TLL)row * CC + c] = hi;
            ol[(TLL)row * CC + c] = lo;
        } else {
            oh[(TLL)row * CC + c] = __float2bfloat16(o);
        }
    }
}

// ---------------- transpose fp32 -> bf16 ([K,N] -> [N,K]) ------------------
template <bool DUAL>
__global__ void transpose_conv(const float* __restrict__ in,
                               bf16* __restrict__ oh, bf16* __restrict__ ol,
                               int ldin, int ldout) {
    __shared__ float t[32][33];
    int k0 = blockIdx.y * 32, n0 = blockIdx.x * 32;
    int tx = threadIdx.x, ty = threadIdx.y;
#pragma unroll
    for (int i = 0; i < 32; i += 8)
        t[ty + i][tx] = in[(TLL)(k0 + ty + i) * ldin + (n0 + tx)];
    __syncthreads();
#pragma unroll
    for (int i = 0; i < 32; i += 8) {
        TLL o = (TLL)(n0 + ty + i) * ldout + (k0 + tx);
        if (DUAL) {
            bf16 hi, lo; split_bf(t[tx][ty + i], hi, lo);
            oh[o] = hi; ol[o] = lo;
        } else {
            oh[o] = __float2bfloat16(t[tx][ty + i]);
        }
    }
}

// ---------------- fused flash attention -----------------------------------
// grid (16, 1, 64): z = b*16 + h, x = 128-row Q block. 256 threads, 8 warps,
// each warp owns 16 Q rows. K/V tiles 128x64, double buffered. y out: bf16 hi.
__global__ void __launch_bounds__(256)
flash_attn(const bf16* __restrict__ qkv, bf16* __restrict__ yh) {
    constexpr int RS = 72;                     // bf16 per smem row
    constexpr int TILE = 128 * RS * 2;         // bytes per 128x64 tile
    extern __shared__ __align__(16) bf16 fsm[];
    const uint32_t sQ  = smem_u32(fsm);
    const uint32_t sKV = sQ + TILE;

    const int tid = threadIdx.x, lane = tid & 31, wid = tid >> 5;
    const int lq = lane >> 2, lr = lane & 3;
    const int z = blockIdx.z, bz = z >> 4, hz = z & 15;
    const int t0 = blockIdx.x * 128;

    const bf16* Qg = qkv + ((TLL)bz * TT + t0) * (3 * CC) + hz * HD;
    const bf16* Kg = qkv + ((TLL)bz * TT) * (3 * CC) + CC + hz * HD;
    const bf16* Vg = Kg + CC;

#pragma unroll
    for (int t = 0; t < 4; t++) {
        int idx = tid + (t << 8);
        int r = idx >> 3, c = idx & 7;
        CP16(sQ + (r * RS + c * 8) * 2, Qg + (TLL)r * (3 * CC) + c * 8);
    }
    asm volatile("cp.async.commit_group;");

    auto stageKV = [&](int buf, int s0) {
        uint32_t base = sKV + buf * (2 * TILE);
#pragma unroll
        for (int t = 0; t < 4; t++) {
            int idx = tid + (t << 8);
            int r = idx >> 3, c = idx & 7;
            CP16(base + (r * RS + c * 8) * 2, Kg + (TLL)(s0 + r) * (3 * CC) + c * 8);
            CP16(base + TILE + (r * RS + c * 8) * 2, Vg + (TLL)(s0 + r) * (3 * CC) + c * 8);
        }
        asm volatile("cp.async.commit_group;");
    };
    stageKV(0, 0);

    uint32_t qf[4][4];
    float y[8][4];
    float m_lo = -1e30f, m_hi = -1e30f, l_lo = 0.f, l_hi = 0.f;
#pragma unroll
    for (int i = 0; i < 8; i++)
#pragma unroll
        for (int q = 0; q < 4; q++) y[i][q] = 0.f;

    const float c_s = 0.125f * 1.4426950408889634f;

    for (int it = 0; it < TT / 128; ++it) {
        if (it + 1 < TT / 128) {
            stageKV((it + 1) & 1, (it + 1) * 128);
            asm volatile("cp.async.wait_group 1;" ::: "memory");
        } else {
            asm volatile("cp.async.wait_group 0;" ::: "memory");
        }
        __syncthreads();

        if (it == 0) {
#pragma unroll
            for (int c = 0; c < 4; c++) {
                uint32_t a = sQ + (((wid * 16) + (lane & 15)) * RS
                                   + c * 16 + ((lane >> 4) & 1) * 8) * 2;
                LDSM4(qf[c], a);
            }
        }

        const uint32_t bbK = sKV + (it & 1) * (2 * TILE);
        const uint32_t bbV = bbK + TILE;

        float S[16][4];
#pragma unroll
        for (int nt = 0; nt < 16; nt++) {
            S[nt][0] = S[nt][1] = S[nt][2] = S[nt][3] = 0.f;
            uint32_t b0[4], b1[4];
            uint32_t a0 = bbK + ((nt * 8 + (lane & 7)) * RS + ((lane >> 3) & 3) * 8) * 2;
            LDSM4(b0, a0);
            LDSM4(b1, a0 + 64);
            mma_bf16(S[nt], qf[0], b0);
            mma_bf16(S[nt], qf[1], b0 + 2);
            mma_bf16(S[nt], qf[2], b1);
            mma_bf16(S[nt], qf[3], b1 + 2);
        }

        float mx0 = -1e30f, mx1 = -1e30f;
#pragma unroll
        for (int nt = 0; nt < 16; nt++) {
            S[nt][0] *= c_s; S[nt][1] *= c_s; S[nt][2] *= c_s; S[nt][3] *= c_s;
            mx0 = fmaxf(mx0, fmaxf(S[nt][0], S[nt][1]));
            mx1 = fmaxf(mx1, fmaxf(S[nt][2], S[nt][3]));
        }
        mx0 = fmaxf(mx0, __shfl_xor_sync(0xffffffffu, mx0, 1));
        mx0 = fmaxf(mx0, __shfl_xor_sync(0xffffffffu, mx0, 2));
        mx1 = fmaxf(mx1, __shfl_xor_sync(0xffffffffu, mx1, 1));
        mx1 = fmaxf(mx1, __shfl_xor_sync(0xffffffffu, mx1, 2));
        float nmlo = fmaxf(m_lo, mx0), nmhi = fmaxf(m_hi, mx1);
        float al = ex2f(m_lo - nmlo), ah = ex2f(m_hi - nmhi);
        m_lo = nmlo; m_hi = nmhi;
        l_lo *= al; l_hi *= ah;
#pragma unroll
        for (int i = 0; i < 8; i++) {
            y[i][0] *= al; y[i][1] *= al; y[i][2] *= ah; y[i][3] *= ah;
        }

        uint32_t pa[8][4];
#pragma unroll
        for (int kc = 0; kc < 8; kc++) {
#pragma unroll
            for (int half = 0; half < 2; half++) {
                int nt = 2 * kc + half;
                float p0 = ex2f(S[nt][0] - m_lo);
                float p1 = ex2f(S[nt][1] - m_lo);
                float p2 = ex2f(S[nt][2] - m_hi);
                float p3 = ex2f(S[nt][3] - m_hi);
                l_lo += p0 + p1; l_hi += p2 + p3;
                __nv_bfloat162 q01 = __floats2bfloat162_rn(p0, p1);
                __nv_bfloat162 q23 = __floats2bfloat162_rn(p2, p3);
                pa[kc][2 * half + 0] = *(uint32_t*)&q01;
                pa[kc][2 * half + 1] = *(uint32_t*)&q23;
            }
        }

#pragma unroll
        for (int kc = 0; kc < 8; kc++) {
#pragma unroll
            for (int np = 0; np < 4; np++) {
                uint32_t vf[4];
                uint32_t a = bbV + ((kc * 16 + ((lane >> 3) & 1) * 8 + (lane & 7)) * RS
                                    + np * 16 + ((lane >> 4) & 1) * 8) * 2;
                LDSM4T(vf, a);
                mma_bf16(y[2 * np], pa[kc], vf);
                mma_bf16(y[2 * np + 1], pa[kc], vf + 2);
            }
        }
        __syncthreads();
    }

    l_lo += __shfl_xor_sync(0xffffffffu, l_lo, 1);
    l_lo += __shfl_xor_sync(0xffffffffu, l_lo, 2);
    l_hi += __shfl_xor_sync(0xffffffffu, l_hi, 1);
    l_hi += __shfl_xor_sync(0xffffffffu, l_hi, 2);
    float inv_lo = 1.f / l_lo, inv_hi = 1.f / l_hi;

    TLL row_lo = (TLL)bz * TT + t0 + wid * 16 + lq;
    TLL row_hi = row_lo + 8;
#pragma unroll
    for (int nt = 0; nt < 8; nt++) {
        int col = hz * HD + nt * 8 + 2 * lr;
        __nv_bfloat162 p0 = __floats2bfloat162_rn(y[nt][0] * inv_lo, y[nt][1] * inv_lo);
        __nv_bfloat162 p1 = __floats2bfloat162_rn(y[nt][2] * inv_hi, y[nt][3] * inv_hi);
        *(__nv_bfloat162*)(yh + row_lo * CC + col) = p0;
        *(__nv_bfloat162*)(yh + row_hi * CC + col) = p1;
    }
}

// ---------------- bf16 mma.sync GEMM (single or x3-split) ------------------
// D[m][n] = scale * sum_k A[m][k]*B[n][k], K-major operands.
// Tile 128 x BN, BK=32, 256 threads, warp grid 2(m) x 4(n).
// flags: 1=+bias, 2=gelu, 4=+residual(fp32), 8=dual bf16 out, 16=hi-only bf16 out
template <int BN, bool SPLIT>
__global__ void __launch_bounds__(256)
bf_gemm(const bf16* __restrict__ Ah, const bf16* __restrict__ Al,
        const bf16* __restrict__ Bh, const bf16* __restrict__ Bl,
        const float* __restrict__ bias, const float* __restrict__ res,
        float* __restrict__ Cf, bf16* __restrict__ Oh, bf16* __restrict__ Ol,
        int K, TLL lda, TLL ldb, TLL ldc,
        float scale, int flags) {
    constexpr int RS = 40;
    constexpr int NARR = SPLIT ? 2 : 1;
    constexpr int A_ELEMS = 128 * RS;
    constexpr int B_ELEMS = BN * RS;
    constexpr int BUF = NARR * (A_ELEMS + B_ELEMS);
    constexpr int WTN = BN / 4;
    constexpr int NI  = WTN / 8;

    extern __shared__ __align__(16) bf16 dynsm[];
    const uint32_t sb = smem_u32(dynsm);

    const int tid = threadIdx.x, lane = tid & 31, wid = tid >> 5;
    const int wm = wid & 1, wn = wid >> 1;

    const TLL rowBase = (TLL)blockIdx.y * 128;
    const TLL colBase = (TLL)blockIdx.x * BN;

    float acc[4][NI][4];
#pragma unroll
    for (int i = 0; i < 4; i++)
#pragma unroll
        for (int j = 0; j < NI; j++)
#pragma unroll
            for (int q = 0; q < 4; q++) acc[i][j][q] = 0.f;

    auto stage = [&](int buf, int k0) {
        const uint32_t bb = sb + buf * (BUF * 2);
#pragma unroll
        for (int t = 0; t < 2 * NARR; t++) {
            int idx = tid + (t << 8);
            int arr = idx >> 9, i2 = idx & 511;
            int r = i2 >> 2, c = i2 & 3;
            const bf16* g = (arr ? Al : Ah) + (rowBase + r) * lda + (k0 + c * 8);
            uint32_t d = bb + (arr * A_ELEMS + r * RS + c * 8) * 2;
            CP16(d, g);
        }
#pragma unroll
        for (int t = 0; t < NARR * BN / 64; t++) {
            int idx = tid + (t << 8);
            int arr = idx / (BN * 4), i2 = idx % (BN * 4);
            int r = i2 >> 2, c = i2 & 3;
            const bf16* g = (arr ? Bl : Bh) + (colBase + r) * ldb + (k0 + c * 8);
            uint32_t d = bb + (NARR * A_ELEMS + arr * B_ELEMS + r * RS + c * 8) * 2;
            CP16(d, g);
        }
        asm volatile("cp.async.commit_group;");
    };

    const int iters = K / 32;
    int buf = 0;
    stage(0, 0);

    for (int it = 0; it < iters; ++it) {
        if (it + 1 < iters) {
            stage(buf ^ 1, (it + 1) * 32);
            asm volatile("cp.async.wait_group 1;" ::: "memory");
        } else {
            asm volatile("cp.async.wait_group 0;" ::: "memory");
        }
        __syncthreads();

        const uint32_t bb = sb + buf * (BUF * 2);
        const uint32_t aRow = (wm * 64 + (lane & 15)) * RS * 2 + ((lane >> 4) << 4);
        const uint32_t bRow = (wn * WTN + (lane & 7)) * RS * 2 + (((lane >> 3) & 1) << 4);

#pragma unroll
        for (int ks = 0; ks < 2; ks++) {
            uint32_t bh[NI][2], bl[NI][2];
#pragma unroll
            for (int ni = 0; ni < NI; ni++) {
                uint32_t ba = bb + NARR * A_ELEMS * 2 + bRow + ni * (8 * RS * 2) + ks * 32;
                LDSM2(bh[ni], ba);
                if (SPLIT) LDSM2(bl[ni], ba + B_ELEMS * 2);
            }
#pragma unroll
            for (int mi = 0; mi < 4; mi++) {
                uint32_t aa = bb + aRow + mi * (16 * RS * 2) + ks * 32;
                uint32_t ah[4], al[4];
                LDSM4(ah, aa);
                if (SPLIT) LDSM4(al, aa + A_ELEMS * 2);
#pragma unroll
                for (int ni = 0; ni < NI; ni++) {
                    if (SPLIT) {
                        mma_bf16(acc[mi][ni], al, bh[ni]);
                        mma_bf16(acc[mi][ni], ah, bl[ni]);
                    }
                    mma_bf16(acc[mi][ni], ah, bh[ni]);
                }
            }
        }
        __syncthreads();
        buf ^= 1;
    }

    const int lq = lane >> 2, lr = lane & 3;
#pragma unroll
    for (int mi = 0; mi < 4; mi++) {
        TLL r0 = rowBase + wm * 64 + mi * 16 + lq;
#pragma unroll
        for (int ni = 0; ni < NI; ni++) {
            TLL c = colBase + wn * WTN + ni * 8 + 2 * lr;
            float v00 = acc[mi][ni][0] * scale, v01 = acc[mi][ni][1] * scale;
            float v10 = acc[mi][ni][2] * scale, v11 = acc[mi][ni][3] * scale;
            if (flags & 1) {
                float b0 = bias[c], b1 = bias[c + 1];
                v00 += b0; v01 += b1; v10 += b0; v11 += b1;
            }
            if (flags & 2) {
                v00 = gelu_f(v00); v01 = gelu_f(v01);
                v10 = gelu_f(v10); v11 = gelu_f(v11);
            }
            if (flags & 4) {
                float2 ra = *(const float2*)(res + r0 * ldc + c);
                float2 rb = *(const float2*)(res + (r0 + 8) * ldc + c);
                v00 += ra.x; v01 += ra.y; v10 += rb.x; v11 += rb.y;
            }
            if (flags & 8) {
                bf16 h0, l0, h1, l1;
                __nv_bfloat162 ph, pl;
                split_bf(v00, h0, l0); split_bf(v01, h1, l1);
                ph.x = h0; ph.y = h1; pl.x = l0; pl.y = l1;
                *(__nv_bfloat162*)(Oh + r0 * ldc + c) = ph;
                *(__nv_bfloat162*)(Ol + r0 * ldc + c) = pl;
                split_bf(v10, h0, l0); split_bf(v11, h1, l1);
                ph.x = h0; ph.y = h1; pl.x = l0; pl.y = l1;
                *(__nv_bfloat162*)(Oh + (r0 + 8) * ldc + c) = ph;
                *(__nv_bfloat162*)(Ol + (r0 + 8) * ldc + c) = pl;
            } else if (flags & 16) {
                *(__nv_bfloat162*)(Oh + r0 * ldc + c) = __floats2bfloat162_rn(v00, v01);
                *(__nv_bfloat162*)(Oh + (r0 + 8) * ldc + c) = __floats2bfloat162_rn(v10, v11);
            } else {
                *(float2*)(Cf + r0 * ldc + c) = make_float2(v00, v01);
                *(float2*)(Cf + (r0 + 8) * ldc + c) = make_float2(v10, v11);
            }
        }
    }
}

// ---------------- launch ----------------
extern "C" void kernel_launch(void* const* d_in, const int* in_sizes, int n_in,
                              void* d_out, int out_size) {
    const float* x          = (const float*)d_in[0];
    const float* ln1_g      = (const float*)d_in[1];
    const float* ln1_b      = (const float*)d_in[2];
    const float* w_qkv      = (const float*)d_in[3];
    const float* b_qkv      = (const float*)d_in[4];
    const float* w_attnproj = (const float*)d_in[5];
    const float* b_attnproj = (const float*)d_in[6];
    const float* ln2_g      = (const float*)d_in[7];
    const float* ln2_b      = (const float*)d_in[8];
    const float* w_fc       = (const float*)d_in[9];
    const float* b_fc       = (const float*)d_in[10];
    const float* w_proj     = (const float*)d_in[11];
    const float* b_proj     = (const float*)d_in[12];
    float* out = (float*)d_out;

    float *x1;
    bf16 *h_hi, *qkv_hi, *y_hi, *h2_hi, *h2_lo, *ff_hi, *ff_lo;
    bf16 *wqkvT_hi, *wapT_hi, *wfcT_hi, *wfcT_lo, *wprjT_hi, *wprjT_lo;
    cudaGetSymbolAddress((void**)&x1,   g_x1);
    cudaGetSymbolAddress((void**)&h_hi, g_h_hi);
    cudaGetSymbolAddress((void**)&qkv_hi, g_qkv_hi);
    cudaGetSymbolAddress((void**)&y_hi, g_y_hi);
    cudaGetSymbolAddress((void**)&h2_hi, g_h2_hi); cudaGetSymbolAddress((void**)&h2_lo, g_h2_lo);
    cudaGetSymbolAddress((void**)&ff_hi, g_ff_hi); cudaGetSymbolAddress((void**)&ff_lo, g_ff_lo);
    cudaGetSymbolAddress((void**)&wqkvT_hi, g_wqkvT_hi);
    cudaGetSymbolAddress((void**)&wapT_hi, g_wapT_hi);
    cudaGetSymbolAddress((void**)&wfcT_hi, g_wfcT_hi);   cudaGetSymbolAddress((void**)&wfcT_lo, g_wfcT_lo);
    cudaGetSymbolAddress((void**)&wprjT_hi, g_wprjT_hi); cudaGetSymbolAddress((void**)&wprjT_lo, g_wprjT_lo);

    static bool attr_done = false;
    if (!attr_done) {
        cudaFuncSetAttribute(bf_gemm<128, true>,  cudaFuncAttributeMaxDynamicSharedMemorySize, 81920);
        cudaFuncSetAttribute(bf_gemm<128, false>, cudaFuncAttributeMaxDynamicSharedMemorySize, 40960);
        cudaFuncSetAttribute(flash_attn,          cudaFuncAttributeMaxDynamicSharedMemorySize, 92160);
        attr_done = true;
    }
    const int SMS = 81920, SM1 = 40960, SMFA = 92160;

    dim3 tb(32, 8);
    transpose_conv<false><<<dim3(3 * CC / 32, CC / 32), tb>>>(w_qkv, wqkvT_hi, nullptr, 3 * CC, CC);
    transpose_conv<false><<<dim3(CC / 32, CC / 32), tb>>>(w_attnproj, wapT_hi, nullptr, CC, CC);
    transpose_conv<true><<<dim3(DFF / 32, CC / 32), tb>>>(w_fc, wfcT_hi, wfcT_lo, DFF, CC);
    transpose_conv<true><<<dim3(CC / 32, DFF / 32), tb>>>(w_proj, wprjT_hi, wprjT_lo, CC, DFF);

    // 1) h = LN1(x)  (hi only)
    ln_kernel<false><<<ROWS, 256>>>(x, ln1_g, ln1_b, h_hi, nullptr);

    // 2) qkv = h @ w_qkv + b_qkv  (plain bf16, hi out)
    bf_gemm<128, false><<<dim3(3 * CC / 128, ROWS / 128, 1), 256, SM1>>>(
        h_hi, nullptr, wqkvT_hi, nullptr, b_qkv, nullptr,
        nullptr, qkv_hi, nullptr, CC,
        CC, CC, 3 * CC, 1.0f, 1 | 16);

    // 3-6) fused attention: y = softmax(QK^T/8) V  (hi out)
    flash_attn<<<dim3(TT / 128, 1, BB * HH), 256, SMFA>>>(qkv_hi, y_hi);

    // 7) x1 = x + y @ w_attnproj + b  (plain bf16, fp32 out)
    bf_gemm<128, false><<<dim3(CC / 128, ROWS / 128, 1), 256, SM1>>>(
        y_hi, nullptr, wapT_hi, nullptr, b_attnproj, x,
        x1, nullptr, nullptr, CC,
        CC, CC, CC, 1.0f, 1 | 4);

    // 8) h2 = LN2(x1)  (dual)
    ln_kernel<true><<<ROWS, 256>>>(x1, ln2_g, ln2_b, h2_hi, h2_lo);

    // 9) ff = gelu(h2 @ w_fc + b_fc)  (x3 split, dual out)
    bf_gemm<128, true><<<dim3(DFF / 128, ROWS / 128, 1), 256, SMS>>>(
        h2_hi, h2_lo, wfcT_hi, wfcT_lo, b_fc, nullptr,
        nullptr, ff_hi, ff_lo, CC,
        CC, CC, DFF, 1.0f, 1 | 2 | 8);

    // 10) out = x1 + ff @ w_proj + b_proj  (x3 split, fp32 out)
    bf_gemm<128, true><<<dim3(CC / 128, ROWS / 128, 1), 256, SMS>>>(
        ff_hi, ff_lo, wprjT_hi, wprjT_lo, b_proj, x1,
        out, nullptr, nullptr, DFF,
        DFF, DFF, CC, 1.0f, 1 | 4);
}

// round 10
// speedup vs baseline: 5.8171x; 1.2352x over previous
#include <cuda_runtime.h>
#include <cuda_fp16.h>
#include <math.h>
#include <stdint.h>

typedef long long TLL;
typedef __half f16;

// ---------------- problem constants ----------------
#define BB   4
#define TT   2048
#define CC   1024
#define HH   16
#define HD   64
#define DFF  4096
#define ROWS (BB*TT)          // 8192

// ---------------- scratch ----------------
__device__ float g_x1  [(TLL)ROWS*CC];          // residual 1 (fp32)

__device__ f16 g_h_hi [(TLL)ROWS*CC];
__device__ f16 g_qkv_hi[(TLL)ROWS*3*CC];
__device__ f16 g_y_hi [(TLL)ROWS*CC];
__device__ f16 g_h2_hi[(TLL)ROWS*CC],      g_h2_lo[(TLL)ROWS*CC];
__device__ f16 g_ff_hi[(TLL)ROWS*DFF],     g_ff_lo[(TLL)ROWS*DFF];
__device__ f16 g_wqkvT_hi[(TLL)3*CC*CC];
__device__ f16 g_wapT_hi [(TLL)CC*CC];
__device__ f16 g_wfcT_hi [(TLL)DFF*CC];
__device__ f16 g_wprjT_hi[(TLL)CC*DFF];

// ---------------- helpers ----------------
__device__ __forceinline__ uint32_t smem_u32(const void* p) {
    return (uint32_t)__cvta_generic_to_shared(p);
}
__device__ __forceinline__ float tanh_ap(float x) {
    float y; asm("tanh.approx.f32 %0, %1;" : "=f"(y) : "f"(x)); return y;
}
__device__ __forceinline__ float gelu_f(float x) {
    const float c = 0.7978845608028654f;
    float t = tanh_ap(c * (x + 0.044715f * x * x * x));
    return 0.5f * x * (1.0f + t);
}
__device__ __forceinline__ float ex2f(float x) {
    float y; asm("ex2.approx.f32 %0, %1;" : "=f"(y) : "f"(x)); return y;
}
__device__ __forceinline__ void split_h(float v, f16& h, f16& l) {
    h = __float2half_rn(v);
    l = __float2half_rn(v - __half2float(h));
}
__device__ __forceinline__ void mma_f16(float* d, const uint32_t* a, const uint32_t* b) {
    asm volatile(
        "mma.sync.aligned.m16n8k16.row.col.f32.f16.f16.f32 "
        "{%0,%1,%2,%3}, {%4,%5,%6,%7}, {%8,%9}, {%0,%1,%2,%3};"
        : "+f"(d[0]), "+f"(d[1]), "+f"(d[2]), "+f"(d[3])
        : "r"(a[0]), "r"(a[1]), "r"(a[2]), "r"(a[3]), "r"(b[0]), "r"(b[1]));
}
#define LDSM4(r, addr) \
    asm volatile("ldmatrix.sync.aligned.m8n8.x4.shared.b16 {%0,%1,%2,%3}, [%4];" \
        : "=r"((r)[0]), "=r"((r)[1]), "=r"((r)[2]), "=r"((r)[3]) : "r"(addr))
#define LDSM4T(r, addr) \
    asm volatile("ldmatrix.sync.aligned.m8n8.x4.trans.shared.b16 {%0,%1,%2,%3}, [%4];" \
        : "=r"((r)[0]), "=r"((r)[1]), "=r"((r)[2]), "=r"((r)[3]) : "r"(addr))
#define LDSM2(r, addr) \
    asm volatile("ldmatrix.sync.aligned.m8n8.x2.shared.b16 {%0,%1}, [%2];" \
        : "=r"((r)[0]), "=r"((r)[1]) : "r"(addr))
#define CP16(dst, src) \
    asm volatile("cp.async.cg.shared.global [%0], [%1], 16;" :: "r"(dst), "l"(src))

// ---------------- LayerNorm variants ----------------
template <bool DUAL>
__global__ void ln_kernel(const float* __restrict__ x,
                          const float* __restrict__ g,
                          const float* __restrict__ b,
                          f16* __restrict__ oh, f16* __restrict__ ol) {
    const int row = blockIdx.x;
    const float* xr = x + (TLL)row * CC;
    float v[4]; float s = 0.f, ss = 0.f;
#pragma unroll
    for (int i = 0; i < 4; i++) {
        v[i] = xr[threadIdx.x + 256 * i];
        s += v[i]; ss += v[i] * v[i];
    }
#pragma unroll
    for (int o = 16; o; o >>= 1) {
        s  += __shfl_xor_sync(0xffffffffu, s, o);
        ss += __shfl_xor_sync(0xffffffffu, ss, o);
    }
    __shared__ float sh0[8], sh1[8];
    int w = threadIdx.x >> 5, l = threadIdx.x & 31;
    if (!l) { sh0[w] = s; sh1[w] = ss; }
    __syncthreads();
    if (threadIdx.x == 0) {
        float S = 0.f, SS = 0.f;
#pragma unroll
        for (int i = 0; i < 8; i++) { S += sh0[i]; SS += sh1[i]; }
        float mu = S * (1.0f / CC);
        float var = SS * (1.0f / CC) - mu * mu;
        sh0[0] = mu; sh1[0] = rsqrtf(var + 1e-5f);
    }
    __syncthreads();
    float mu = sh0[0], rstd = sh1[0];
#pragma unroll
    for (int i = 0; i < 4; i++) {
        int c = threadIdx.x + 256 * i;
        float o = (v[i] - mu) * rstd * g[c] + b[c];
        if (DUAL) {
            f16 hi, lo; split_h(o, hi, lo);
            oh[(TLL)row * CC + c] = hi;
            ol[(TLL)row * CC + c] = lo;
        } else {
            oh[(TLL)row * CC + c] = __float2half_rn(o);
        }
    }
}

// ---------------- transpose fp32 -> fp16 hi ([K,N] -> [N,K]) ---------------
__global__ void transpose_conv(const float* __restrict__ in,
                               f16* __restrict__ oh, int ldin, int ldout) {
    __shared__ float t[32][33];
    int k0 = blockIdx.y * 32, n0 = blockIdx.x * 32;
    int tx = threadIdx.x, ty = threadIdx.y;
#pragma unroll
    for (int i = 0; i < 32; i += 8)
        t[ty + i][tx] = in[(TLL)(k0 + ty + i) * ldin + (n0 + tx)];
    __syncthreads();
#pragma unroll
    for (int i = 0; i < 32; i += 8)
        oh[(TLL)(n0 + ty + i) * ldout + (k0 + tx)] = __float2half_rn(t[tx][ty + i]);
}

// ---------------- fused flash attention -----------------------------------
// grid (16, 1, 64): z = b*16 + h, x = 128-row Q block. 256 threads, 8 warps,
// each warp owns 16 Q rows. K/V tiles 128x64, double buffered. y out: f16 hi.
__global__ void __launch_bounds__(256)
flash_attn(const f16* __restrict__ qkv, f16* __restrict__ yh) {
    constexpr int RS = 72;                     // f16 per smem row
    constexpr int TILE = 128 * RS * 2;         // bytes per 128x64 tile
    extern __shared__ __align__(16) f16 fsm[];
    const uint32_t sQ  = smem_u32(fsm);
    const uint32_t sKV = sQ + TILE;

    const int tid = threadIdx.x, lane = tid & 31, wid = tid >> 5;
    const int lq = lane >> 2, lr = lane & 3;
    const int z = blockIdx.z, bz = z >> 4, hz = z & 15;
    const int t0 = blockIdx.x * 128;

    const f16* Qg = qkv + ((TLL)bz * TT + t0) * (3 * CC) + hz * HD;
    const f16* Kg = qkv + ((TLL)bz * TT) * (3 * CC) + CC + hz * HD;
    const f16* Vg = Kg + CC;

#pragma unroll
    for (int t = 0; t < 4; t++) {
        int idx = tid + (t << 8);
        int r = idx >> 3, c = idx & 7;
        CP16(sQ + (r * RS + c * 8) * 2, Qg + (TLL)r * (3 * CC) + c * 8);
    }
    asm volatile("cp.async.commit_group;");

    auto stageKV = [&](int buf, int s0) {
        uint32_t base = sKV + buf * (2 * TILE);
#pragma unroll
        for (int t = 0; t < 4; t++) {
            int idx = tid + (t << 8);
            int r = idx >> 3, c = idx & 7;
            CP16(base + (r * RS + c * 8) * 2, Kg + (TLL)(s0 + r) * (3 * CC) + c * 8);
            CP16(base + TILE + (r * RS + c * 8) * 2, Vg + (TLL)(s0 + r) * (3 * CC) + c * 8);
        }
        asm volatile("cp.async.commit_group;");
    };
    stageKV(0, 0);

    uint32_t qf[4][4];
    float y[8][4];
    float m_lo = -1e30f, m_hi = -1e30f, l_lo = 0.f, l_hi = 0.f;
#pragma unroll
    for (int i = 0; i < 8; i++)
#pragma unroll
        for (int q = 0; q < 4; q++) y[i][q] = 0.f;

    const float c_s = 0.125f * 1.4426950408889634f;

    for (int it = 0; it < TT / 128; ++it) {
        if (it + 1 < TT / 128) {
            stageKV((it + 1) & 1, (it + 1) * 128);
            asm volatile("cp.async.wait_group 1;" ::: "memory");
        } else {
            asm volatile("cp.async.wait_group 0;" ::: "memory");
        }
        __syncthreads();

        if (it == 0) {
#pragma unroll
            for (int c = 0; c < 4; c++) {
                uint32_t a = sQ + (((wid * 16) + (lane & 15)) * RS
                                   + c * 16 + ((lane >> 4) & 1) * 8) * 2;
                LDSM4(qf[c], a);
            }
        }

        const uint32_t bbK = sKV + (it & 1) * (2 * TILE);
        const uint32_t bbV = bbK + TILE;

        float S[16][4];
#pragma unroll
        for (int nt = 0; nt < 16; nt++) {
            S[nt][0] = S[nt][1] = S[nt][2] = S[nt][3] = 0.f;
            uint32_t b0[4], b1[4];
            uint32_t a0 = bbK + ((nt * 8 + (lane & 7)) * RS + ((lane >> 3) & 3) * 8) * 2;
            LDSM4(b0, a0);
            LDSM4(b1, a0 + 64);
            mma_f16(S[nt], qf[0], b0);
            mma_f16(S[nt], qf[1], b0 + 2);
            mma_f16(S[nt], qf[2], b1);
            mma_f16(S[nt], qf[3], b1 + 2);
        }

        float mx0 = -1e30f, mx1 = -1e30f;
#pragma unroll
        for (int nt = 0; nt < 16; nt++) {
            S[nt][0] *= c_s; S[nt][1] *= c_s; S[nt][2] *= c_s; S[nt][3] *= c_s;
            mx0 = fmaxf(mx0, fmaxf(S[nt][0], S[nt][1]));
            mx1 = fmaxf(mx1, fmaxf(S[nt][2], S[nt][3]));
        }
        mx0 = fmaxf(mx0, __shfl_xor_sync(0xffffffffu, mx0, 1));
        mx0 = fmaxf(mx0, __shfl_xor_sync(0xffffffffu, mx0, 2));
        mx1 = fmaxf(mx1, __shfl_xor_sync(0xffffffffu, mx1, 1));
        mx1 = fmaxf(mx1, __shfl_xor_sync(0xffffffffu, mx1, 2));
        float nmlo = fmaxf(m_lo, mx0), nmhi = fmaxf(m_hi, mx1);
        float al = ex2f(m_lo - nmlo), ah = ex2f(m_hi - nmhi);
        m_lo = nmlo; m_hi = nmhi;
        l_lo *= al; l_hi *= ah;
#pragma unroll
        for (int i = 0; i < 8; i++) {
            y[i][0] *= al; y[i][1] *= al; y[i][2] *= ah; y[i][3] *= ah;
        }

        uint32_t pa[8][4];
#pragma unroll
        for (int kc = 0; kc < 8; kc++) {
#pragma unroll
            for (int half = 0; half < 2; half++) {
                int nt = 2 * kc + half;
                float p0 = ex2f(S[nt][0] - m_lo);
                float p1 = ex2f(S[nt][1] - m_lo);
                float p2 = ex2f(S[nt][2] - m_hi);
                float p3 = ex2f(S[nt][3] - m_hi);
                l_lo += p0 + p1; l_hi += p2 + p3;
                __half2 q01 = __floats2half2_rn(p0, p1);
                __half2 q23 = __floats2half2_rn(p2, p3);
                pa[kc][2 * half + 0] = *(uint32_t*)&q01;
                pa[kc][2 * half + 1] = *(uint32_t*)&q23;
            }
        }

#pragma unroll
        for (int kc = 0; kc < 8; kc++) {
#pragma unroll
            for (int np = 0; np < 4; np++) {
                uint32_t vf[4];
                uint32_t a = bbV + ((kc * 16 + ((lane >> 3) & 1) * 8 + (lane & 7)) * RS
                                    + np * 16 + ((lane >> 4) & 1) * 8) * 2;
                LDSM4T(vf, a);
                mma_f16(y[2 * np], pa[kc], vf);
                mma_f16(y[2 * np + 1], pa[kc], vf + 2);
            }
        }
        __syncthreads();
    }

    l_lo += __shfl_xor_sync(0xffffffffu, l_lo, 1);
    l_lo += __shfl_xor_sync(0xffffffffu, l_lo, 2);
    l_hi += __shfl_xor_sync(0xffffffffu, l_hi, 1);
    l_hi += __shfl_xor_sync(0xffffffffu, l_hi, 2);
    float inv_lo = 1.f / l_lo, inv_hi = 1.f / l_hi;

    TLL row_lo = (TLL)bz * TT + t0 + wid * 16 + lq;
    TLL row_hi = row_lo + 8;
#pragma unroll
    for (int nt = 0; nt < 8; nt++) {
        int col = hz * HD + nt * 8 + 2 * lr;
        __half2 p0 = __floats2half2_rn(y[nt][0] * inv_lo, y[nt][1] * inv_lo);
        __half2 p1 = __floats2half2_rn(y[nt][2] * inv_hi, y[nt][3] * inv_hi);
        *(__half2*)(yh + row_lo * CC + col) = p0;
        *(__half2*)(yh + row_hi * CC + col) = p1;
    }
}

// ---------------- fp16 mma.sync GEMM ---------------------------------------
// D[m][n] = scale * sum_k A[m][k]*B[n][k], K-major operands.
// SPLITA: A = Ah + Al (2 MMAs: Al*Bh + Ah*Bh). B always hi-only fp16.
// Tile 128 x BN, BK=32, 256 threads, warp grid 2(m) x 4(n).
// flags: 1=+bias, 2=gelu, 4=+residual(fp32), 8=dual f16 out, 16=hi-only f16 out
template <int BN, bool SPLITA>
__global__ void __launch_bounds__(256)
hf_gemm(const f16* __restrict__ Ah, const f16* __restrict__ Al,
        const f16* __restrict__ Bh,
        const float* __restrict__ bias, const float* __restrict__ res,
        float* __restrict__ Cf, f16* __restrict__ Oh, f16* __restrict__ Ol,
        int K, TLL lda, TLL ldb, TLL ldc,
        float scale, int flags) {
    constexpr int RS = 40;
    constexpr int NA = SPLITA ? 2 : 1;
    constexpr int A_ELEMS = 128 * RS;
    constexpr int B_ELEMS = BN * RS;
    constexpr int BUF = NA * A_ELEMS + B_ELEMS;
    constexpr int WTN = BN / 4;
    constexpr int NI  = WTN / 8;

    extern __shared__ __align__(16) f16 dynsm[];
    const uint32_t sb = smem_u32(dynsm);

    const int tid = threadIdx.x, lane = tid & 31, wid = tid >> 5;
    const int wm = wid & 1, wn = wid >> 1;

    const TLL rowBase = (TLL)blockIdx.y * 128;
    const TLL colBase = (TLL)blockIdx.x * BN;

    float acc[4][NI][4];
#pragma unroll
    for (int i = 0; i < 4; i++)
#pragma unroll
        for (int j = 0; j < NI; j++)
#pragma unroll
            for (int q = 0; q < 4; q++) acc[i][j][q] = 0.f;

    auto stage = [&](int buf, int k0) {
        const uint32_t bb = sb + buf * (BUF * 2);
#pragma unroll
        for (int t = 0; t < 2 * NA; t++) {          // A: NA arrays x 512 chunks
            int idx = tid + (t << 8);
            int arr = idx >> 9, i2 = idx & 511;
            int r = i2 >> 2, c = i2 & 3;
            const f16* g = (arr ? Al : Ah) + (rowBase + r) * lda + (k0 + c * 8);
            uint32_t d = bb + (arr * A_ELEMS + r * RS + c * 8) * 2;
            CP16(d, g);
        }
#pragma unroll
        for (int t = 0; t < BN / 64; t++) {         // B: 1 array x BN*4 chunks
            int idx = tid + (t << 8);
            int r = idx >> 2, c = idx & 3;
            const f16* g = Bh + (colBase + r) * ldb + (k0 + c * 8);
            uint32_t d = bb + (NA * A_ELEMS + r * RS + c * 8) * 2;
            CP16(d, g);
        }
        asm volatile("cp.async.commit_group;");
    };

    const int iters = K / 32;
    int buf = 0;
    stage(0, 0);

    for (int it = 0; it < iters; ++it) {
        if (it + 1 < iters) {
            stage(buf ^ 1, (it + 1) * 32);
            asm volatile("cp.async.wait_group 1;" ::: "memory");
        } else {
            asm volatile("cp.async.wait_group 0;" ::: "memory");
        }
        __syncthreads();

        const uint32_t bb = sb + buf * (BUF * 2);
        const uint32_t aRow = (wm * 64 + (lane & 15)) * RS * 2 + ((lane >> 4) << 4);
        const uint32_t bRow = (wn * WTN + (lane & 7)) * RS * 2 + (((lane >> 3) & 1) << 4);

#pragma unroll
        for (int ks = 0; ks < 2; ks++) {
            uint32_t bh[NI][2];
#pragma unroll
            for (int ni = 0; ni < NI; ni++) {
                uint32_t ba = bb + NA * A_ELEMS * 2 + bRow + ni * (8 * RS * 2) + ks * 32;
                LDSM2(bh[ni], ba);
            }
#pragma unroll
            for (int mi = 0; mi < 4; mi++) {
                uint32_t aa = bb + aRow + mi * (16 * RS * 2) + ks * 32;
                uint32_t ah[4], al[4];
                LDSM4(ah, aa);
                if (SPLITA) LDSM4(al, aa + A_ELEMS * 2);
#pragma unroll
                for (int ni = 0; ni < NI; ni++) {
                    if (SPLITA) mma_f16(acc[mi][ni], al, bh[ni]);
                    mma_f16(acc[mi][ni], ah, bh[ni]);
                }
            }
        }
        __syncthreads();
        buf ^= 1;
    }

    const int lq = lane >> 2, lr = lane & 3;
#pragma unroll
    for (int mi = 0; mi < 4; mi++) {
        TLL r0 = rowBase + wm * 64 + mi * 16 + lq;
#pragma unroll
        for (int ni = 0; ni < NI; ni++) {
            TLL c = colBase + wn * WTN + ni * 8 + 2 * lr;
            float v00 = acc[mi][ni][0] * scale, v01 = acc[mi][ni][1] * scale;
            float v10 = acc[mi][ni][2] * scale, v11 = acc[mi][ni][3] * scale;
            if (flags & 1) {
                float b0 = bias[c], b1 = bias[c + 1];
                v00 += b0; v01 += b1; v10 += b0; v11 += b1;
            }
            if (flags & 2) {
                v00 = gelu_f(v00); v01 = gelu_f(v01);
                v10 = gelu_f(v10); v11 = gelu_f(v11);
            }
            if (flags & 4) {
                float2 ra = *(const float2*)(res + r0 * ldc + c);
                float2 rb = *(const float2*)(res + (r0 + 8) * ldc + c);
                v00 += ra.x; v01 += ra.y; v10 += rb.x; v11 += rb.y;
            }
            if (flags & 8) {
                f16 h0, l0, h1, l1;
                __half2 ph, pl;
                split_h(v00, h0, l0); split_h(v01, h1, l1);
                ph = __halves2half2(h0, h1); pl = __halves2half2(l0, l1);
                *(__half2*)(Oh + r0 * ldc + c) = ph;
                *(__half2*)(Ol + r0 * ldc + c) = pl;
                split_h(v10, h0, l0); split_h(v11, h1, l1);
                ph = __halves2half2(h0, h1); pl = __halves2half2(l0, l1);
                *(__half2*)(Oh + (r0 + 8) * ldc + c) = ph;
                *(__half2*)(Ol + (r0 + 8) * ldc + c) = pl;
            } else if (flags & 16) {
                *(__half2*)(Oh + r0 * ldc + c) = __floats2half2_rn(v00, v01);
                *(__half2*)(Oh + (r0 + 8) * ldc + c) = __floats2half2_rn(v10, v11);
            } else {
                *(float2*)(Cf + r0 * ldc + c) = make_float2(v00, v01);
                *(float2*)(Cf + (r0 + 8) * ldc + c) = make_float2(v10, v11);
            }
        }
    }
}

// ---------------- launch ----------------
extern "C" void kernel_launch(void* const* d_in, const int* in_sizes, int n_in,
                              void* d_out, int out_size) {
    const float* x          = (const float*)d_in[0];
    const float* ln1_g      = (const float*)d_in[1];
    const float* ln1_b      = (const float*)d_in[2];
    const float* w_qkv      = (const float*)d_in[3];
    const float* b_qkv      = (const float*)d_in[4];
    const float* w_attnproj = (const float*)d_in[5];
    const float* b_attnproj = (const float*)d_in[6];
    const float* ln2_g      = (const float*)d_in[7];
    const float* ln2_b      = (const float*)d_in[8];
    const float* w_fc       = (const float*)d_in[9];
    const float* b_fc       = (const float*)d_in[10];
    const float* w_proj     = (const float*)d_in[11];
    const float* b_proj     = (const float*)d_in[12];
    float* out = (float*)d_out;

    float *x1;
    f16 *h_hi, *qkv_hi, *y_hi, *h2_hi, *h2_lo, *ff_hi, *ff_lo;
    f16 *wqkvT_hi, *wapT_hi, *wfcT_hi, *wprjT_hi;
    cudaGetSymbolAddress((void**)&x1,   g_x1);
    cudaGetSymbolAddress((void**)&h_hi, g_h_hi);
    cudaGetSymbolAddress((void**)&qkv_hi, g_qkv_hi);
    cudaGetSymbolAddress((void**)&y_hi, g_y_hi);
    cudaGetSymbolAddress((void**)&h2_hi, g_h2_hi); cudaGetSymbolAddress((void**)&h2_lo, g_h2_lo);
    cudaGetSymbolAddress((void**)&ff_hi, g_ff_hi); cudaGetSymbolAddress((void**)&ff_lo, g_ff_lo);
    cudaGetSymbolAddress((void**)&wqkvT_hi, g_wqkvT_hi);
    cudaGetSymbolAddress((void**)&wapT_hi, g_wapT_hi);
    cudaGetSymbolAddress((void**)&wfcT_hi, g_wfcT_hi);
    cudaGetSymbolAddress((void**)&wprjT_hi, g_wprjT_hi);

    static bool attr_done = false;
    if (!attr_done) {
        cudaFuncSetAttribute(hf_gemm<128, true>,  cudaFuncAttributeMaxDynamicSharedMemorySize, 61440);
        cudaFuncSetAttribute(hf_gemm<128, false>, cudaFuncAttributeMaxDynamicSharedMemorySize, 40960);
        cudaFuncSetAttribute(flash_attn,          cudaFuncAttributeMaxDynamicSharedMemorySize, 92160);
        attr_done = true;
    }
    const int SM2 = 61440, SM1 = 40960, SMFA = 92160;

    dim3 tb(32, 8);
    transpose_conv<<<dim3(3 * CC / 32, CC / 32), tb>>>(w_qkv, wqkvT_hi, 3 * CC, CC);
    transpose_conv<<<dim3(CC / 32, CC / 32), tb>>>(w_attnproj, wapT_hi, CC, CC);
    transpose_conv<<<dim3(DFF / 32, CC / 32), tb>>>(w_fc, wfcT_hi, DFF, CC);
    transpose_conv<<<dim3(CC / 32, DFF / 32), tb>>>(w_proj, wprjT_hi, CC, DFF);

    // 1) h = LN1(x)  (hi only)
    ln_kernel<false><<<ROWS, 256>>>(x, ln1_g, ln1_b, h_hi, nullptr);

    // 2) qkv = h @ w_qkv + b_qkv  (plain fp16, hi out)
    hf_gemm<128, false><<<dim3(3 * CC / 128, ROWS / 128, 1), 256, SM1>>>(
        h_hi, nullptr, wqkvT_hi, b_qkv, nullptr,
        nullptr, qkv_hi, nullptr, CC,
        CC, CC, 3 * CC, 1.0f, 1 | 16);

    // 3-6) fused attention: y = softmax(QK^T/8) V  (hi out)
    flash_attn<<<dim3(TT / 128, 1, BB * HH), 256, SMFA>>>(qkv_hi, y_hi);

    // 7) x1 = x + y @ w_attnproj + b  (plain fp16, fp32 out)
    hf_gemm<128, false><<<dim3(CC / 128, ROWS / 128, 1), 256, SM1>>>(
        y_hi, nullptr, wapT_hi, b_attnproj, x,
        x1, nullptr, nullptr, CC,
        CC, CC, CC, 1.0f, 1 | 4);

    // 8) h2 = LN2(x1)  (dual fp16)
    ln_kernel<true><<<ROWS, 256>>>(x1, ln2_g, ln2_b, h2_hi, h2_lo);

    // 9) ff = gelu(h2 @ w_fc + b_fc)  (A-split x2, dual out)
    hf_gemm<128, true><<<dim3(DFF / 128, ROWS / 128, 1), 256, SM2>>>(
        h2_hi, h2_lo, wfcT_hi, b_fc, nullptr,
        nullptr, ff_hi, ff_lo, CC,
        CC, CC, DFF, 1.0f, 1 | 2 | 8);

    // 10) out = x1 + ff @ w_proj + b_proj  (A-split x2, fp32 out)
    hf_gemm<128, true><<<dim3(CC / 128, ROWS / 128, 1), 256, SM2>>>(
        ff_hi, ff_lo, wprjT_hi, b_proj, x1,
        out, nullptr, nullptr, DFF,
        DFF, DFF, CC, 1.0f, 1 | 4);
}